// round 13
// baseline (speedup 1.0000x reference)
#include <cuda_runtime.h>
#include <cuda_bf16.h>
#include <stdint.h>

#define DIM   128
#define HEADS 4
#define HD    32
#define NTOK  128
#define BWIN  2048
#define NMASK 256
#define SCALEF 0.1767766952966369f
#define PAD   136

// merged bias plane: mask + sp_mask + rpb per (w,h)
__device__ float g_cmrp[(size_t)NMASK * HEADS * NTOK * NTOK];
// split hi/lo bf16 planes: [b,h][t][16 uint32 = 32 bf16], 64B rows
__device__ uint32_t g_qph[(size_t)BWIN * HEADS * NTOK * 16];
__device__ uint32_t g_qpl[(size_t)BWIN * HEADS * NTOK * 16];
__device__ uint32_t g_kph[(size_t)BWIN * HEADS * NTOK * 16];
__device__ uint32_t g_kpl[(size_t)BWIN * HEADS * NTOK * 16];
__device__ uint32_t g_vph[(size_t)BWIN * HEADS * NTOK * 16];
__device__ uint32_t g_vpl[(size_t)BWIN * HEADS * NTOK * 16];
// packed ctx: [b][t][64 dpairs] uint2{hi01, lo01}
__device__ uint2 g_ctxp[(size_t)BWIN * NTOK * 64];
__device__ uint4 g_wqkv_h[6144], g_wqkv_l[6144];
__device__ uint4 g_wproj_h[2048], g_wproj_l[2048];

// ---------- helpers ----------
__device__ __forceinline__ uint32_t smem_u32(const void* p) {
    uint32_t a;
    asm("{ .reg .u64 t; cvta.to.shared.u64 t, %1; cvt.u32.u64 %0, t; }" : "=r"(a) : "l"(p));
    return a;
}
__device__ __forceinline__ uint32_t pk2(float a, float b) {
    __nv_bfloat162 t = __floats2bfloat162_rn(a, b);
    return *reinterpret_cast<uint32_t*>(&t);
}
__device__ __forceinline__ float bfh(float x) {
    return __bfloat162float(__float2bfloat16(x));
}
#define LDM4(r, addr) \
    asm volatile("ldmatrix.sync.aligned.m8n8.x4.shared.b16 {%0,%1,%2,%3}, [%4];" \
                 : "=r"((r)[0]), "=r"((r)[1]), "=r"((r)[2]), "=r"((r)[3]) : "r"(addr))
#define LDM4T(r, addr) \
    asm volatile("ldmatrix.sync.aligned.m8n8.x4.trans.shared.b16 {%0,%1,%2,%3}, [%4];" \
                 : "=r"((r)[0]), "=r"((r)[1]), "=r"((r)[2]), "=r"((r)[3]) : "r"(addr))
#define MMA(d, a, b0, b1) \
    asm volatile("mma.sync.aligned.m16n8k16.row.col.f32.bf16.bf16.f32 " \
                 "{%0,%1,%2,%3}, {%4,%5,%6,%7}, {%8,%9}, {%0,%1,%2,%3};" \
                 : "+f"((d)[0]), "+f"((d)[1]), "+f"((d)[2]), "+f"((d)[3]) \
                 : "r"((a)[0]), "r"((a)[1]), "r"((a)[2]), "r"((a)[3]), "r"(b0), "r"(b1))
// interleaved 3-term pair: even/odd acc chains alternate (dep distance 2),
// per-acc term order (hh, hl, lh) preserved -> numerics identical
#define MMA6(de, do_, a_h, a_l, bh, bl) \
    do { \
        MMA(de,  a_h, (bh)[0], (bh)[1]);  MMA(do_, a_h, (bh)[2], (bh)[3]); \
        MMA(de,  a_h, (bl)[0], (bl)[1]);  MMA(do_, a_h, (bl)[2], (bl)[3]); \
        MMA(de,  a_l, (bh)[0], (bh)[1]);  MMA(do_, a_l, (bh)[2], (bh)[3]); \
    } while (0)
#define STS2(addr, a, b) \
    asm volatile("st.shared.v2.b32 [%0], {%1, %2};" :: "r"(addr), "r"(a), "r"(b))
#define CPA16(dst, src) \
    asm volatile("cp.async.cg.shared.global [%0], [%1], 16;" :: "r"(dst), "l"(src))
#define CPA_COMMIT() asm volatile("cp.async.commit_group;" ::: "memory")
#define CPA_WAIT1()  asm volatile("cp.async.wait_group 1;" ::: "memory")
#define CPA_WAIT0()  asm volatile("cp.async.wait_group 0;" ::: "memory")

#define SM_XL   34816
#define WBUF_SZ 34816u
#define GEMM_SMEM 104448

// ---------- prep ----------
__global__ void prep_cmrp_kernel(const float* __restrict__ m, const float* __restrict__ s,
                                 const int* __restrict__ rpi, const float* __restrict__ bt) {
    int gi = (blockIdx.x * 256 + threadIdx.x) * 4;
    int w = gi >> 14, i = gi & 16383;
    float4 a = *(const float4*)(m + (size_t)w * 16384 + i);
    float4 c = *(const float4*)(s + (size_t)w * 16384 + i);
    a.x += c.x; a.y += c.y; a.z += c.z; a.w += c.w;
    int4 r = *(const int4*)(rpi + i);
#pragma unroll
    for (int h = 0; h < HEADS; ++h) {
        float4 o = make_float4(a.x + __ldg(bt + r.x * 4 + h), a.y + __ldg(bt + r.y * 4 + h),
                               a.z + __ldg(bt + r.z * 4 + h), a.w + __ldg(bt + r.w * 4 + h));
        *(float4*)(g_cmrp + (((size_t)w * 4 + h) << 14) + i) = o;
    }
}
__global__ void conv_w_kernel(const float* __restrict__ w, int n, int which) {
    int i = blockIdx.x * 256 + threadIdx.x;
    if (i >= n) return;
    int row = i >> 4, c0 = (i & 15) * 8;
    const float* wr = w + row * DIM + c0;
    float4 v0 = *(const float4*)(wr), v1 = *(const float4*)(wr + 4);
    uint4 hv = make_uint4(pk2(v0.x, v0.y), pk2(v0.z, v0.w), pk2(v1.x, v1.y), pk2(v1.z, v1.w));
    uint4 lv = make_uint4(pk2(v0.x - bfh(v0.x), v0.y - bfh(v0.y)),
                          pk2(v0.z - bfh(v0.z), v0.w - bfh(v0.w)),
                          pk2(v1.x - bfh(v1.x), v1.y - bfh(v1.y)),
                          pk2(v1.z - bfh(v1.z), v1.w - bfh(v1.w)));
    if (which == 0) { g_wqkv_h[i] = hv; g_wqkv_l[i] = lv; }
    else            { g_wproj_h[i] = hv; g_wproj_l[i] = lv; }
}

// ---------- GEMM pieces ----------
__device__ __forceinline__ void conv_A(const float* __restrict__ src, uint32_t XH, int tid) {
    for (int i = tid; i < 4096; i += 256) {
        int t = i >> 5, c = (i & 31) * 4;
        float4 v = *(const float4*)(src + t * DIM + c);
        uint32_t o = XH + (uint32_t)(t * PAD + c) * 2u;
        STS2(o, pk2(v.x, v.y), pk2(v.z, v.w));
        STS2(o + SM_XL, pk2(v.x - bfh(v.x), v.y - bfh(v.y)),
             pk2(v.z - bfh(v.z), v.w - bfh(v.w)));
    }
}
__device__ __forceinline__ void fill_A_packed(const uint4* __restrict__ cp, uint32_t XH, int tid) {
    for (int i = tid; i < 4096; i += 256) {
        int t = i >> 5, p2 = i & 31;
        uint4 v = __ldg(cp + i);
        uint32_t o = XH + (uint32_t)(t * 272 + p2 * 8);
        STS2(o, v.x, v.z);
        STS2(o + SM_XL, v.y, v.w);
    }
}
__device__ __forceinline__ void cpW_async(const uint4* __restrict__ gh,
                                          const uint4* __restrict__ gl,
                                          uint32_t wb, int tid) {
    for (int i = tid; i < 1024; i += 256) {
        int row = i >> 4, c8 = i & 15;
        uint32_t o = wb + (uint32_t)(row * 272 + c8 * 16);
        CPA16(o, gh + i);
        CPA16(o + 17408, gl + i);
    }
}

// 2-window GEMM: A frags for both windows in regs, B loaded once feeds both.
// MODE 0: qkv epilogue (split hi/lo planes); MODE 1: proj (fp32 out + bias)
template <int NCHUNK, int MODE>
__device__ __forceinline__ void gemm_mma2(const float* __restrict__ xsrc0,
                                          const float* __restrict__ xsrc1,
                                          const uint4* __restrict__ wh,
                                          const uint4* __restrict__ wl,
                                          const float* __restrict__ bias,
                                          float* __restrict__ gen_out, int b0) {
    extern __shared__ unsigned char sraw[];
    uint32_t XH = smem_u32(sraw);
    int tid = threadIdx.x, wid = tid >> 5, lane = tid & 31;

    int r0 = wid * 16;
    int lr = lane & 15, kh = (lane >> 4) & 1;
    int brow = ((lane >> 4) & 1) * 8 + (lane & 7);
    int bseg = (lane >> 3) & 1;
    uint32_t abase = XH + (uint32_t)((r0 + lr) * PAD + kh * 8) * 2u;
    uint32_t boff = (uint32_t)(brow * 272 + bseg * 16);

    // hoist A fragments for BOTH windows (X buffer reused)
    uint32_t ah[2][8][4], al[2][8][4];
#pragma unroll
    for (int w = 0; w < 2; ++w) {
        if (MODE == 0) conv_A(w == 0 ? xsrc0 : xsrc1, XH, tid);
        else           fill_A_packed((const uint4*)g_ctxp + (size_t)(b0 + w) * 4096, XH, tid);
        __syncthreads();
#pragma unroll
        for (int k = 0; k < 8; ++k) {
            LDM4(ah[w][k], abase + (uint32_t)(k * 32));
            LDM4(al[w][k], abase + SM_XL + (uint32_t)(k * 32));
        }
        __syncthreads();   // all warps done reading before next fill / W reuse
    }

    cpW_async(wh, wl, XH, tid);
    CPA_COMMIT();
    if (NCHUNK > 1) { cpW_async(wh + 1024, wl + 1024, XH + WBUF_SZ, tid); CPA_COMMIT(); }

    for (int ch = 0; ch < NCHUNK; ++ch) {
        if (ch + 1 < NCHUNK) CPA_WAIT1(); else CPA_WAIT0();
        __syncthreads();
        if (ch + 2 < NCHUNK) {
            cpW_async(wh + (ch + 2) * 1024, wl + (ch + 2) * 1024,
                      XH + (uint32_t)(((ch + 2) % 3) * WBUF_SZ), tid);
            CPA_COMMIT();
        }
        uint32_t bbase = XH + (uint32_t)((ch % 3) * WBUF_SZ) + boff;

        float acc[2][8][4];
#pragma unroll
        for (int w = 0; w < 2; ++w)
#pragma unroll
            for (int nt = 0; nt < 8; ++nt)
#pragma unroll
                for (int j = 0; j < 4; ++j) acc[w][nt][j] = 0.f;
#pragma unroll
        for (int k = 0; k < 8; ++k) {
#pragma unroll
            for (int ntp = 0; ntp < 4; ++ntp) {
                uint32_t ba = bbase + (uint32_t)(ntp * 16 * 272 + k * 32);
                uint32_t bh[4], bl[4];
                LDM4(bh, ba);
                LDM4(bl, ba + 17408);
                MMA6(acc[0][2 * ntp], acc[0][2 * ntp + 1], ah[0][k], al[0][k], bh, bl);
                MMA6(acc[1][2 * ntp], acc[1][2 * ntp + 1], ah[1][k], al[1][k], bh, bl);
            }
        }

        int t0 = r0 + (lane >> 2);
#pragma unroll
        for (int w = 0; w < 2; ++w) {
            int b = b0 + w;
#pragma unroll
            for (int nt = 0; nt < 8; ++nt) {
                int f = ch * 64 + nt * 8 + (lane & 3) * 2;
                float bx = __ldg(bias + f), by = __ldg(bias + f + 1);
                if (MODE == 0) {
                    int s = f >> 7, h = (f >> 5) & 3, dpair = (f & 31) >> 1;
                    float sc = (s == 0) ? SCALEF : 1.0f;
                    uint32_t* ph = (s == 0 ? g_qph : s == 1 ? g_kph : g_vph);
                    uint32_t* pl = (s == 0 ? g_qpl : s == 1 ? g_kpl : g_vpl);
                    size_t off = (((size_t)b * HEADS + h) * NTOK + t0) * 16 + dpair;
                    float v0 = (acc[w][nt][0] + bx) * sc, v1 = (acc[w][nt][1] + by) * sc;
                    ph[off] = pk2(v0, v1);
                    pl[off] = pk2(v0 - bfh(v0), v1 - bfh(v1));
                    float v2 = (acc[w][nt][2] + bx) * sc, v3 = (acc[w][nt][3] + by) * sc;
                    ph[off + 8 * 16] = pk2(v2, v3);
                    pl[off + 8 * 16] = pk2(v2 - bfh(v2), v3 - bfh(v3));
                } else {
                    *(float2*)(gen_out + ((size_t)b * NTOK + t0) * DIM + f) =
                        make_float2(acc[w][nt][0] + bx, acc[w][nt][1] + by);
                    *(float2*)(gen_out + ((size_t)b * NTOK + t0 + 8) * DIM + f) =
                        make_float2(acc[w][nt][2] + bx, acc[w][nt][3] + by);
                }
            }
        }
    }
}
__global__ __launch_bounds__(256, 1)
void qkv_mma_kernel(const float* __restrict__ x, const float* __restrict__ b_qkv) {
    int b0 = blockIdx.x * 2;
    gemm_mma2<6, 0>(x + (size_t)b0 * NTOK * DIM, x + (size_t)(b0 + 1) * NTOK * DIM,
                    g_wqkv_h, g_wqkv_l, b_qkv, nullptr, b0);
}
__global__ __launch_bounds__(256, 1)
void proj_mma_kernel(const float* __restrict__ b_proj, float* __restrict__ out) {
    gemm_mma2<2, 1>(nullptr, nullptr, g_wproj_h, g_wproj_l, b_proj, out, blockIdx.x * 2);
}

// ---------- attention (unchanged) ----------
#define A_QH 0u
#define A_QL 10240u
#define A_KH 20480u
#define A_KL 30720u
#define A_VH 40960u
#define A_VL 51200u
#define ATT_SMEM 61440

__device__ __forceinline__ void cp_plane(uint32_t dst, const uint32_t* __restrict__ src, int tid) {
#pragma unroll
    for (int r = 0; r < 2; ++r) {
        int i = tid + r * 256;
        int t = i >> 2, seg = i & 3;
        CPA16(dst + (uint32_t)(t * 80 + seg * 16), src + (size_t)t * 16 + seg * 4);
    }
}

__global__ __launch_bounds__(256, 2)
void att_mma_kernel() {
    int b = blockIdx.x, h = blockIdx.y;
    extern __shared__ unsigned char sraw[];
    uint32_t sb = smem_u32(sraw);

    int tid = threadIdx.x, lane = tid & 31, wid = tid >> 5;
    size_t pbase = ((size_t)b * HEADS + h) * (NTOK * 16);

    cp_plane(sb + A_QH, g_qph + pbase, tid);
    cp_plane(sb + A_QL, g_qpl + pbase, tid);
    cp_plane(sb + A_KH, g_kph + pbase, tid);
    cp_plane(sb + A_KL, g_kpl + pbase, tid);
    cp_plane(sb + A_VH, g_vph + pbase, tid);
    cp_plane(sb + A_VL, g_vpl + pbase, tid);
    CPA_COMMIT();
    CPA_WAIT0();
    __syncthreads();

    int r0 = wid * 16;
    int lr = lane & 15, khf = (lane >> 4) & 1;
    int brow = ((lane >> 4) & 1) * 8 + (lane & 7);
    int bseg = (lane >> 3) & 1;
    uint32_t qa = sb + A_QH + (uint32_t)((r0 + lr) * 80 + khf * 16);
    uint32_t ka = sb + A_KH + (uint32_t)(brow * 80 + bseg * 16);
    int vrow = (lane & 7) + ((lane >> 3) & 1) * 8;
    uint32_t va = sb + A_VH + (uint32_t)(vrow * 80 + ((lane >> 4) & 1) * 16);

    uint32_t ah[2][4], al[2][4];
#pragma unroll
    for (int k = 0; k < 2; ++k) {
        LDM4(ah[k], qa + (uint32_t)(k * 32));
        LDM4(al[k], qa + (A_QL - A_QH) + (uint32_t)(k * 32));
    }

    float sacc[16][4];
#pragma unroll
    for (int j = 0; j < 16; ++j)
#pragma unroll
        for (int c = 0; c < 4; ++c) sacc[j][c] = 0.f;
#pragma unroll
    for (int ntp = 0; ntp < 8; ++ntp) {
#pragma unroll
        for (int k = 0; k < 2; ++k) {
            uint32_t ba = ka + (uint32_t)(ntp * 16 * 80 + k * 32);
            uint32_t bh[4], bl[4];
            LDM4(bh, ba);
            LDM4(bl, ba + (A_KL - A_KH));
            MMA6(sacc[2 * ntp], sacc[2 * ntp + 1], ah[k], al[k], bh, bl);
        }
    }

    int g = lane >> 2, q2 = (lane & 3) * 2;
    int row0 = r0 + g;
    const float* cm = g_cmrp + (((size_t)(b & (NMASK - 1)) * HEADS + h) << 14)
                    + row0 * NTOK + q2;
#pragma unroll
    for (int j = 0; j < 16; ++j) {
        float2 c0 = *(const float2*)(cm + j * 8);
        float2 c1 = *(const float2*)(cm + 8 * NTOK + j * 8);
        sacc[j][0] += c0.x;  sacc[j][1] += c0.y;
        sacc[j][2] += c1.x;  sacc[j][3] += c1.y;
    }

    float mx0 = -1e30f, mx1 = -1e30f;
#pragma unroll
    for (int j = 0; j < 16; ++j) {
        mx0 = fmaxf(mx0, fmaxf(sacc[j][0], sacc[j][1]));
        mx1 = fmaxf(mx1, fmaxf(sacc[j][2], sacc[j][3]));
    }
    mx0 = fmaxf(mx0, __shfl_xor_sync(0xffffffffu, mx0, 1));
    mx0 = fmaxf(mx0, __shfl_xor_sync(0xffffffffu, mx0, 2));
    mx1 = fmaxf(mx1, __shfl_xor_sync(0xffffffffu, mx1, 1));
    mx1 = fmaxf(mx1, __shfl_xor_sync(0xffffffffu, mx1, 2));
    float s0 = 0.f, s1 = 0.f;
#pragma unroll
    for (int j = 0; j < 16; ++j) {
        sacc[j][0] = __expf(sacc[j][0] - mx0);
        sacc[j][1] = __expf(sacc[j][1] - mx0);
        sacc[j][2] = __expf(sacc[j][2] - mx1);
        sacc[j][3] = __expf(sacc[j][3] - mx1);
        s0 += sacc[j][0] + sacc[j][1];
        s1 += sacc[j][2] + sacc[j][3];
    }
    s0 += __shfl_xor_sync(0xffffffffu, s0, 1);
    s0 += __shfl_xor_sync(0xffffffffu, s0, 2);
    s1 += __shfl_xor_sync(0xffffffffu, s1, 1);
    s1 += __shfl_xor_sync(0xffffffffu, s1, 2);
    float inv0 = 1.0f / s0, inv1 = 1.0f / s1;

    float oacc[4][4];
#pragma unroll
    for (int dn = 0; dn < 4; ++dn)
#pragma unroll
        for (int c = 0; c < 4; ++c) oacc[dn][c] = 0.f;
#pragma unroll
    for (int kk = 0; kk < 8; ++kk) {
        float p00 = sacc[2 * kk][0],     p01 = sacc[2 * kk][1];
        float p10 = sacc[2 * kk][2],     p11 = sacc[2 * kk][3];
        float p20 = sacc[2 * kk + 1][0], p21 = sacc[2 * kk + 1][1];
        float p30 = sacc[2 * kk + 1][2], p31 = sacc[2 * kk + 1][3];
        uint32_t aH[4], aL[4];
        aH[0] = pk2(p00, p01); aH[1] = pk2(p10, p11);
        aH[2] = pk2(p20, p21); aH[3] = pk2(p30, p31);
        aL[0] = pk2(p00 - bfh(p00), p01 - bfh(p01));
        aL[1] = pk2(p10 - bfh(p10), p11 - bfh(p11));
        aL[2] = pk2(p20 - bfh(p20), p21 - bfh(p21));
        aL[3] = pk2(p30 - bfh(p30), p31 - bfh(p31));
#pragma unroll
        for (int dnp = 0; dnp < 2; ++dnp) {
            uint32_t ba = va + (uint32_t)(kk * 16 * 80 + dnp * 32);
            uint32_t bh[4], bl[4];
            LDM4T(bh, ba);
            LDM4T(bl, ba + (A_VL - A_VH));
            MMA6(oacc[2 * dnp], oacc[2 * dnp + 1], aH, aL, bh, bl);
        }
    }

    uint2* cp0 = g_ctxp + ((size_t)b * NTOK + row0) * 64 + h * 16 + (lane & 3);
#pragma unroll
    for (int dn = 0; dn < 4; ++dn) {
        float v0 = oacc[dn][0] * inv0, v1 = oacc[dn][1] * inv0;
        cp0[dn * 4] = make_uint2(pk2(v0, v1), pk2(v0 - bfh(v0), v1 - bfh(v1)));
        float v2 = oacc[dn][2] * inv1, v3 = oacc[dn][3] * inv1;
        cp0[8 * 64 + dn * 4] = make_uint2(pk2(v2, v3), pk2(v2 - bfh(v2), v3 - bfh(v3)));
    }
}

// ---------- launch ----------
extern "C" void kernel_launch(void* const* d_in, const int* in_sizes, int n_in,
                              void* d_out, int out_size) {
    const float* x          = (const float*)d_in[0];
    const int*   rpi        = (const int*)d_in[1];
    const float* mask       = (const float*)d_in[2];
    const float* sp_mask    = (const float*)d_in[3];
    const float* w_qkv      = (const float*)d_in[4];
    const float* b_qkv      = (const float*)d_in[5];
    const float* bias_table = (const float*)d_in[6];
    const float* w_proj     = (const float*)d_in[7];
    const float* b_proj     = (const float*)d_in[8];
    float* out = (float*)d_out;

    cudaFuncSetAttribute((const void*)qkv_mma_kernel,
                         cudaFuncAttributeMaxDynamicSharedMemorySize, GEMM_SMEM);
    cudaFuncSetAttribute((const void*)proj_mma_kernel,
                         cudaFuncAttributeMaxDynamicSharedMemorySize, GEMM_SMEM);
    cudaFuncSetAttribute((const void*)att_mma_kernel,
                         cudaFuncAttributeMaxDynamicSharedMemorySize, ATT_SMEM);

    prep_cmrp_kernel<<<4096, 256>>>(mask, sp_mask, rpi, bias_table);
    conv_w_kernel<<<24, 256>>>(w_qkv, 6144, 0);
    conv_w_kernel<<<8, 256>>>(w_proj, 2048, 1);
    qkv_mma_kernel<<<BWIN / 2, 256, GEMM_SMEM>>>(x, b_qkv);
    att_mma_kernel<<<dim3(BWIN, HEADS), 256, ATT_SMEM>>>();
    proj_mma_kernel<<<BWIN / 2, 256, GEMM_SMEM>>>(b_proj, out);
}

// round 14
// speedup vs baseline: 1.1093x; 1.1093x over previous
#include <cuda_runtime.h>
#include <cuda_bf16.h>
#include <stdint.h>

#define DIM   128
#define HEADS 4
#define HD    32
#define NTOK  128
#define BWIN  2048
#define NMASK 256
#define SCALEF 0.1767766952966369f
#define PAD   136

// merged bias plane: mask + sp_mask + rpb per (w,h)
__device__ float g_cmrp[(size_t)NMASK * HEADS * NTOK * NTOK];
// q,k: hi-only bf16 planes; v: hi+lo
__device__ uint32_t g_qph[(size_t)BWIN * HEADS * NTOK * 16];
__device__ uint32_t g_kph[(size_t)BWIN * HEADS * NTOK * 16];
__device__ uint32_t g_vph[(size_t)BWIN * HEADS * NTOK * 16];
__device__ uint32_t g_vpl[(size_t)BWIN * HEADS * NTOK * 16];
// packed ctx: [b][t][64 dpairs] uint2{hi01, lo01}
__device__ uint2 g_ctxp[(size_t)BWIN * NTOK * 64];
__device__ uint4 g_wqkv_h[6144], g_wqkv_l[6144];
__device__ uint4 g_wproj_h[2048], g_wproj_l[2048];

// ---------- helpers ----------
__device__ __forceinline__ uint32_t smem_u32(const void* p) {
    uint32_t a;
    asm("{ .reg .u64 t; cvta.to.shared.u64 t, %1; cvt.u32.u64 %0, t; }" : "=r"(a) : "l"(p));
    return a;
}
__device__ __forceinline__ uint32_t pk2(float a, float b) {
    __nv_bfloat162 t = __floats2bfloat162_rn(a, b);
    return *reinterpret_cast<uint32_t*>(&t);
}
__device__ __forceinline__ float bfh(float x) {
    return __bfloat162float(__float2bfloat16(x));
}
#define LDM4(r, addr) \
    asm volatile("ldmatrix.sync.aligned.m8n8.x4.shared.b16 {%0,%1,%2,%3}, [%4];" \
                 : "=r"((r)[0]), "=r"((r)[1]), "=r"((r)[2]), "=r"((r)[3]) : "r"(addr))
#define LDM4T(r, addr) \
    asm volatile("ldmatrix.sync.aligned.m8n8.x4.trans.shared.b16 {%0,%1,%2,%3}, [%4];" \
                 : "=r"((r)[0]), "=r"((r)[1]), "=r"((r)[2]), "=r"((r)[3]) : "r"(addr))
#define MMA(d, a, b0, b1) \
    asm volatile("mma.sync.aligned.m16n8k16.row.col.f32.bf16.bf16.f32 " \
                 "{%0,%1,%2,%3}, {%4,%5,%6,%7}, {%8,%9}, {%0,%1,%2,%3};" \
                 : "+f"((d)[0]), "+f"((d)[1]), "+f"((d)[2]), "+f"((d)[3]) \
                 : "r"((a)[0]), "r"((a)[1]), "r"((a)[2]), "r"((a)[3]), "r"(b0), "r"(b1))
// 3-term pair (hh, hl, lh per acc) and 2-term pair (hh, hl = ah·(bh+bl))
#define MMA6(de, do_, a_h, a_l, bh, bl) \
    do { \
        MMA(de,  a_h, (bh)[0], (bh)[1]);  MMA(do_, a_h, (bh)[2], (bh)[3]); \
        MMA(de,  a_h, (bl)[0], (bl)[1]);  MMA(do_, a_h, (bl)[2], (bl)[3]); \
        MMA(de,  a_l, (bh)[0], (bh)[1]);  MMA(do_, a_l, (bh)[2], (bh)[3]); \
    } while (0)
#define MMA4(de, do_, a_h, bh, bl) \
    do { \
        MMA(de,  a_h, (bh)[0], (bh)[1]);  MMA(do_, a_h, (bh)[2], (bh)[3]); \
        MMA(de,  a_h, (bl)[0], (bl)[1]);  MMA(do_, a_h, (bl)[2], (bl)[3]); \
    } while (0)
#define STS2(addr, a, b) \
    asm volatile("st.shared.v2.b32 [%0], {%1, %2};" :: "r"(addr), "r"(a), "r"(b))
#define CPA16(dst, src) \
    asm volatile("cp.async.cg.shared.global [%0], [%1], 16;" :: "r"(dst), "l"(src))
#define CPA_COMMIT() asm volatile("cp.async.commit_group;" ::: "memory")
#define CPA_WAIT1()  asm volatile("cp.async.wait_group 1;" ::: "memory")
#define CPA_WAIT0()  asm volatile("cp.async.wait_group 0;" ::: "memory")

#define SM_XL   34816
#define WBUF_SZ 34816u
#define GEMM_SMEM 104448

// ---------- prep ----------
__global__ void prep_cmrp_kernel(const float* __restrict__ m, const float* __restrict__ s,
                                 const int* __restrict__ rpi, const float* __restrict__ bt) {
    int gi = (blockIdx.x * 256 + threadIdx.x) * 4;
    int w = gi >> 14, i = gi & 16383;
    float4 a = *(const float4*)(m + (size_t)w * 16384 + i);
    float4 c = *(const float4*)(s + (size_t)w * 16384 + i);
    a.x += c.x; a.y += c.y; a.z += c.z; a.w += c.w;
    int4 r = *(const int4*)(rpi + i);
#pragma unroll
    for (int h = 0; h < HEADS; ++h) {
        float4 o = make_float4(a.x + __ldg(bt + r.x * 4 + h), a.y + __ldg(bt + r.y * 4 + h),
                               a.z + __ldg(bt + r.z * 4 + h), a.w + __ldg(bt + r.w * 4 + h));
        *(float4*)(g_cmrp + (((size_t)w * 4 + h) << 14) + i) = o;
    }
}
__global__ void conv_w_kernel(const float* __restrict__ w, int n, int which) {
    int i = blockIdx.x * 256 + threadIdx.x;
    if (i >= n) return;
    int row = i >> 4, c0 = (i & 15) * 8;
    const float* wr = w + row * DIM + c0;
    float4 v0 = *(const float4*)(wr), v1 = *(const float4*)(wr + 4);
    uint4 hv = make_uint4(pk2(v0.x, v0.y), pk2(v0.z, v0.w), pk2(v1.x, v1.y), pk2(v1.z, v1.w));
    uint4 lv = make_uint4(pk2(v0.x - bfh(v0.x), v0.y - bfh(v0.y)),
                          pk2(v0.z - bfh(v0.z), v0.w - bfh(v0.w)),
                          pk2(v1.x - bfh(v1.x), v1.y - bfh(v1.y)),
                          pk2(v1.z - bfh(v1.z), v1.w - bfh(v1.w)));
    if (which == 0) { g_wqkv_h[i] = hv; g_wqkv_l[i] = lv; }
    else            { g_wproj_h[i] = hv; g_wproj_l[i] = lv; }
}

// ---------- GEMM pieces ----------
__device__ __forceinline__ void conv_A(const float* __restrict__ src, uint32_t XH, int tid) {
    for (int i = tid; i < 4096; i += 256) {
        int t = i >> 5, c = (i & 31) * 4;
        float4 v = *(const float4*)(src + t * DIM + c);
        uint32_t o = XH + (uint32_t)(t * PAD + c) * 2u;
        STS2(o, pk2(v.x, v.y), pk2(v.z, v.w));
        STS2(o + SM_XL, pk2(v.x - bfh(v.x), v.y - bfh(v.y)),
             pk2(v.z - bfh(v.z), v.w - bfh(v.w)));
    }
}
__device__ __forceinline__ void fill_A_packed(const uint4* __restrict__ cp, uint32_t XH, int tid) {
    for (int i = tid; i < 4096; i += 256) {
        int t = i >> 5, p2 = i & 31;
        uint4 v = __ldg(cp + i);
        uint32_t o = XH + (uint32_t)(t * 272 + p2 * 8);
        STS2(o, v.x, v.z);
        STS2(o + SM_XL, v.y, v.w);
    }
}
__device__ __forceinline__ void cpW_async(const uint4* __restrict__ gh,
                                          const uint4* __restrict__ gl,
                                          uint32_t wb, int tid) {
    for (int i = tid; i < 1024; i += 256) {
        int row = i >> 4, c8 = i & 15;
        uint32_t o = wb + (uint32_t)(row * 272 + c8 * 16);
        CPA16(o, gh + i);
        CPA16(o + 17408, gl + i);
    }
}

// MODE 0: qkv (q,k chunks 2-term + hi-only store; v chunks 3-term + hi/lo store)
// MODE 1: proj (3-term, fp32 out + bias)
template <int NCHUNK, int MODE>
__device__ __forceinline__ void gemm_mma(const float* __restrict__ xsrc,
                                         const uint4* __restrict__ wh,
                                         const uint4* __restrict__ wl,
                                         const float* __restrict__ bias,
                                         float* __restrict__ gen_out, int b) {
    extern __shared__ unsigned char sraw[];
    uint32_t XH = smem_u32(sraw);
    int tid = threadIdx.x, wid = tid >> 5, lane = tid & 31;
    if (MODE == 0) conv_A(xsrc, XH, tid);
    else           fill_A_packed((const uint4*)g_ctxp + (size_t)b * 4096, XH, tid);
    __syncthreads();

    int r0 = wid * 16;
    int lr = lane & 15, kh = (lane >> 4) & 1;
    int brow = ((lane >> 4) & 1) * 8 + (lane & 7);
    int bseg = (lane >> 3) & 1;
    uint32_t abase = XH + (uint32_t)((r0 + lr) * PAD + kh * 8) * 2u;
    uint32_t boff = (uint32_t)(brow * 272 + bseg * 16);

    uint32_t ah[8][4], al[8][4];
#pragma unroll
    for (int k = 0; k < 8; ++k) {
        LDM4(ah[k], abase + (uint32_t)(k * 32));
        LDM4(al[k], abase + SM_XL + (uint32_t)(k * 32));
    }
    __syncthreads();

    cpW_async(wh, wl, XH, tid);
    CPA_COMMIT();
    if (NCHUNK > 1) { cpW_async(wh + 1024, wl + 1024, XH + WBUF_SZ, tid); CPA_COMMIT(); }

    for (int ch = 0; ch < NCHUNK; ++ch) {
        if (ch + 1 < NCHUNK) CPA_WAIT1(); else CPA_WAIT0();
        __syncthreads();
        if (ch + 2 < NCHUNK) {
            cpW_async(wh + (ch + 2) * 1024, wl + (ch + 2) * 1024,
                      XH + (uint32_t)(((ch + 2) % 3) * WBUF_SZ), tid);
            CPA_COMMIT();
        }
        uint32_t bbase = XH + (uint32_t)((ch % 3) * WBUF_SZ) + boff;
        bool full3 = (MODE == 1) || (ch >= 4);   // v chunks 3-term; q,k 2-term

        float acc[8][4];
#pragma unroll
        for (int nt = 0; nt < 8; ++nt)
#pragma unroll
            for (int j = 0; j < 4; ++j) acc[nt][j] = 0.f;
#pragma unroll
        for (int k = 0; k < 8; ++k) {
#pragma unroll
            for (int ntp = 0; ntp < 4; ++ntp) {
                uint32_t ba = bbase + (uint32_t)(ntp * 16 * 272 + k * 32);
                uint32_t bh[4], bl[4];
                LDM4(bh, ba);
                LDM4(bl, ba + 17408);
                MMA4(acc[2 * ntp], acc[2 * ntp + 1], ah[k], bh, bl);
                if (full3) {
                    MMA(acc[2 * ntp],     al[k], bh[0], bh[1]);
                    MMA(acc[2 * ntp + 1], al[k], bh[2], bh[3]);
                }
            }
        }

        int t0 = r0 + (lane >> 2);
#pragma unroll
        for (int nt = 0; nt < 8; ++nt) {
            int f = ch * 64 + nt * 8 + (lane & 3) * 2;
            float bx = __ldg(bias + f), by = __ldg(bias + f + 1);
            if (MODE == 0) {
                int s = f >> 7, h = (f >> 5) & 3, dpair = (f & 31) >> 1;
                float sc = (s == 0) ? SCALEF : 1.0f;
                uint32_t* ph = (s == 0 ? g_qph : s == 1 ? g_kph : g_vph);
                size_t off = (((size_t)b * HEADS + h) * NTOK + t0) * 16 + dpair;
                float v0 = (acc[nt][0] + bx) * sc, v1 = (acc[nt][1] + by) * sc;
                float v2 = (acc[nt][2] + bx) * sc, v3 = (acc[nt][3] + by) * sc;
                ph[off] = pk2(v0, v1);
                ph[off + 8 * 16] = pk2(v2, v3);
                if (s == 2) {
                    g_vpl[off] = pk2(v0 - bfh(v0), v1 - bfh(v1));
                    g_vpl[off + 8 * 16] = pk2(v2 - bfh(v2), v3 - bfh(v3));
                }
            } else {
                *(float2*)(gen_out + ((size_t)b * NTOK + t0) * DIM + f) =
                    make_float2(acc[nt][0] + bx, acc[nt][1] + by);
                *(float2*)(gen_out + ((size_t)b * NTOK + t0 + 8) * DIM + f) =
                    make_float2(acc[nt][2] + bx, acc[nt][3] + by);
            }
        }
    }
}
__global__ __launch_bounds__(256, 2)
void qkv_mma_kernel(const float* __restrict__ x, const float* __restrict__ b_qkv) {
    gemm_mma<6, 0>(x + (size_t)blockIdx.x * NTOK * DIM, g_wqkv_h, g_wqkv_l, b_qkv,
                   nullptr, blockIdx.x);
}
__global__ __launch_bounds__(256, 2)
void proj_mma_kernel(const float* __restrict__ b_proj, float* __restrict__ out) {
    gemm_mma<2, 1>(nullptr, g_wproj_h, g_wproj_l, b_proj, out, blockIdx.x);
}

// ---------- attention: Q,K hi-only (1-term S), V hi/lo (3-term PV) ----------
#define A_QH 0u
#define A_KH 10240u
#define A_VH 20480u
#define A_VL 30720u
#define ATT_SMEM 40960

__device__ __forceinline__ void cp_plane(uint32_t dst, const uint32_t* __restrict__ src, int tid) {
#pragma unroll
    for (int r = 0; r < 2; ++r) {
        int i = tid + r * 256;
        int t = i >> 2, seg = i & 3;
        CPA16(dst + (uint32_t)(t * 80 + seg * 16), src + (size_t)t * 16 + seg * 4);
    }
}

__global__ __launch_bounds__(256, 2)
void att_mma_kernel() {
    int b = blockIdx.x, h = blockIdx.y;
    extern __shared__ unsigned char sraw[];
    uint32_t sb = smem_u32(sraw);

    int tid = threadIdx.x, lane = tid & 31, wid = tid >> 5;
    size_t pbase = ((size_t)b * HEADS + h) * (NTOK * 16);

    cp_plane(sb + A_QH, g_qph + pbase, tid);
    cp_plane(sb + A_KH, g_kph + pbase, tid);
    cp_plane(sb + A_VH, g_vph + pbase, tid);
    cp_plane(sb + A_VL, g_vpl + pbase, tid);
    CPA_COMMIT();
    CPA_WAIT0();
    __syncthreads();

    int r0 = wid * 16;
    int lr = lane & 15, khf = (lane >> 4) & 1;
    int brow = ((lane >> 4) & 1) * 8 + (lane & 7);
    int bseg = (lane >> 3) & 1;
    uint32_t qa = sb + A_QH + (uint32_t)((r0 + lr) * 80 + khf * 16);
    uint32_t ka = sb + A_KH + (uint32_t)(brow * 80 + bseg * 16);
    int vrow = (lane & 7) + ((lane >> 3) & 1) * 8;
    uint32_t va = sb + A_VH + (uint32_t)(vrow * 80 + ((lane >> 4) & 1) * 16);

    uint32_t ah[2][4];
#pragma unroll
    for (int k = 0; k < 2; ++k) LDM4(ah[k], qa + (uint32_t)(k * 32));

    // ---- S = q k^T, single-term bf16 ----
    float sacc[16][4];
#pragma unroll
    for (int j = 0; j < 16; ++j)
#pragma unroll
        for (int c = 0; c < 4; ++c) sacc[j][c] = 0.f;
#pragma unroll
    for (int ntp = 0; ntp < 8; ++ntp) {
#pragma unroll
        for (int k = 0; k < 2; ++k) {
            uint32_t ba = ka + (uint32_t)(ntp * 16 * 80 + k * 32);
            uint32_t bh[4];
            LDM4(bh, ba);
            MMA(sacc[2 * ntp],     ah[k], bh[0], bh[1]);
            MMA(sacc[2 * ntp + 1], ah[k], bh[2], bh[3]);
        }
    }

    int g = lane >> 2, q2 = (lane & 3) * 2;
    int row0 = r0 + g;
    const float* cm = g_cmrp + (((size_t)(b & (NMASK - 1)) * HEADS + h) << 14)
                    + row0 * NTOK + q2;
#pragma unroll
    for (int j = 0; j < 16; ++j) {
        float2 c0 = *(const float2*)(cm + j * 8);
        float2 c1 = *(const float2*)(cm + 8 * NTOK + j * 8);
        sacc[j][0] += c0.x;  sacc[j][1] += c0.y;
        sacc[j][2] += c1.x;  sacc[j][3] += c1.y;
    }

    float mx0 = -1e30f, mx1 = -1e30f;
#pragma unroll
    for (int j = 0; j < 16; ++j) {
        mx0 = fmaxf(mx0, fmaxf(sacc[j][0], sacc[j][1]));
        mx1 = fmaxf(mx1, fmaxf(sacc[j][2], sacc[j][3]));
    }
    mx0 = fmaxf(mx0, __shfl_xor_sync(0xffffffffu, mx0, 1));
    mx0 = fmaxf(mx0, __shfl_xor_sync(0xffffffffu, mx0, 2));
    mx1 = fmaxf(mx1, __shfl_xor_sync(0xffffffffu, mx1, 1));
    mx1 = fmaxf(mx1, __shfl_xor_sync(0xffffffffu, mx1, 2));
    float s0 = 0.f, s1 = 0.f;
#pragma unroll
    for (int j = 0; j < 16; ++j) {
        sacc[j][0] = __expf(sacc[j][0] - mx0);
        sacc[j][1] = __expf(sacc[j][1] - mx0);
        sacc[j][2] = __expf(sacc[j][2] - mx1);
        sacc[j][3] = __expf(sacc[j][3] - mx1);
        s0 += sacc[j][0] + sacc[j][1];
        s1 += sacc[j][2] + sacc[j][3];
    }
    s0 += __shfl_xor_sync(0xffffffffu, s0, 1);
    s0 += __shfl_xor_sync(0xffffffffu, s0, 2);
    s1 += __shfl_xor_sync(0xffffffffu, s1, 1);
    s1 += __shfl_xor_sync(0xffffffffu, s1, 2);
    float inv0 = 1.0f / s0, inv1 = 1.0f / s1;

    // ---- PV: P hi/lo in-register, V hi/lo (3-term) ----
    float oacc[4][4];
#pragma unroll
    for (int dn = 0; dn < 4; ++dn)
#pragma unroll
        for (int c = 0; c < 4; ++c) oacc[dn][c] = 0.f;
#pragma unroll
    for (int kk = 0; kk < 8; ++kk) {
        float p00 = sacc[2 * kk][0],     p01 = sacc[2 * kk][1];
        float p10 = sacc[2 * kk][2],     p11 = sacc[2 * kk][3];
        float p20 = sacc[2 * kk + 1][0], p21 = sacc[2 * kk + 1][1];
        float p30 = sacc[2 * kk + 1][2], p31 = sacc[2 * kk + 1][3];
        uint32_t aH[4], aL[4];
        aH[0] = pk2(p00, p01); aH[1] = pk2(p10, p11);
        aH[2] = pk2(p20, p21); aH[3] = pk2(p30, p31);
        aL[0] = pk2(p00 - bfh(p00), p01 - bfh(p01));
        aL[1] = pk2(p10 - bfh(p10), p11 - bfh(p11));
        aL[2] = pk2(p20 - bfh(p20), p21 - bfh(p21));
        aL[3] = pk2(p30 - bfh(p30), p31 - bfh(p31));
#pragma unroll
        for (int dnp = 0; dnp < 2; ++dnp) {
            uint32_t ba = va + (uint32_t)(kk * 16 * 80 + dnp * 32);
            uint32_t bh[4], bl[4];
            LDM4T(bh, ba);
            LDM4T(bl, ba + (A_VL - A_VH));
            MMA6(oacc[2 * dnp], oacc[2 * dnp + 1], aH, aL, bh, bl);
        }
    }

    uint2* cp0 = g_ctxp + ((size_t)b * NTOK + row0) * 64 + h * 16 + (lane & 3);
#pragma unroll
    for (int dn = 0; dn < 4; ++dn) {
        float v0 = oacc[dn][0] * inv0, v1 = oacc[dn][1] * inv0;
        cp0[dn * 4] = make_uint2(pk2(v0, v1), pk2(v0 - bfh(v0), v1 - bfh(v1)));
        float v2 = oacc[dn][2] * inv1, v3 = oacc[dn][3] * inv1;
        cp0[8 * 64 + dn * 4] = make_uint2(pk2(v2, v3), pk2(v2 - bfh(v2), v3 - bfh(v3)));
    }
}

// ---------- launch ----------
extern "C" void kernel_launch(void* const* d_in, const int* in_sizes, int n_in,
                              void* d_out, int out_size) {
    const float* x          = (const float*)d_in[0];
    const int*   rpi        = (const int*)d_in[1];
    const float* mask       = (const float*)d_in[2];
    const float* sp_mask    = (const float*)d_in[3];
    const float* w_qkv      = (const float*)d_in[4];
    const float* b_qkv      = (const float*)d_in[5];
    const float* bias_table = (const float*)d_in[6];
    const float* w_proj     = (const float*)d_in[7];
    const float* b_proj     = (const float*)d_in[8];
    float* out = (float*)d_out;

    cudaFuncSetAttribute((const void*)qkv_mma_kernel,
                         cudaFuncAttributeMaxDynamicSharedMemorySize, GEMM_SMEM);
    cudaFuncSetAttribute((const void*)proj_mma_kernel,
                         cudaFuncAttributeMaxDynamicSharedMemorySize, GEMM_SMEM);
    cudaFuncSetAttribute((const void*)att_mma_kernel,
                         cudaFuncAttributeMaxDynamicSharedMemorySize, ATT_SMEM);

    prep_cmrp_kernel<<<4096, 256>>>(mask, sp_mask, rpi, bias_table);
    conv_w_kernel<<<24, 256>>>(w_qkv, 6144, 0);
    conv_w_kernel<<<8, 256>>>(w_proj, 2048, 1);
    qkv_mma_kernel<<<BWIN, 256, GEMM_SMEM>>>(x, b_qkv);
    att_mma_kernel<<<dim3(BWIN, HEADS), 256, ATT_SMEM>>>();
    proj_mma_kernel<<<BWIN, 256, GEMM_SMEM>>>(b_proj, out);
}

// round 15
// speedup vs baseline: 1.1482x; 1.0350x over previous
#include <cuda_runtime.h>
#include <cuda_bf16.h>
#include <stdint.h>

#define DIM   128
#define HEADS 4
#define HD    32
#define NTOK  128
#define BWIN  2048
#define NMASK 256
#define SCALEF 0.1767766952966369f
#define PAD   136

// merged bias plane: mask + sp_mask + rpb per (w,h)
__device__ float g_cmrp[(size_t)NMASK * HEADS * NTOK * NTOK];
// q,k: hi-only bf16 planes; v: hi+lo
__device__ uint32_t g_qph[(size_t)BWIN * HEADS * NTOK * 16];
__device__ uint32_t g_kph[(size_t)BWIN * HEADS * NTOK * 16];
__device__ uint32_t g_vph[(size_t)BWIN * HEADS * NTOK * 16];
__device__ uint32_t g_vpl[(size_t)BWIN * HEADS * NTOK * 16];
// packed ctx: [b][t][64 dpairs] uint2{hi01, lo01}
__device__ uint2 g_ctxp[(size_t)BWIN * NTOK * 64];
__device__ uint4 g_wqkv_h[6144], g_wqkv_l[6144];
__device__ uint4 g_wproj_h[2048], g_wproj_l[2048];

// ---------- helpers ----------
__device__ __forceinline__ uint32_t smem_u32(const void* p) {
    uint32_t a;
    asm("{ .reg .u64 t; cvta.to.shared.u64 t, %1; cvt.u32.u64 %0, t; }" : "=r"(a) : "l"(p));
    return a;
}
__device__ __forceinline__ uint32_t pk2(float a, float b) {
    __nv_bfloat162 t = __floats2bfloat162_rn(a, b);
    return *reinterpret_cast<uint32_t*>(&t);
}
__device__ __forceinline__ float bfh(float x) {
    return __bfloat162float(__float2bfloat16(x));
}
#define LDM4(r, addr) \
    asm volatile("ldmatrix.sync.aligned.m8n8.x4.shared.b16 {%0,%1,%2,%3}, [%4];" \
                 : "=r"((r)[0]), "=r"((r)[1]), "=r"((r)[2]), "=r"((r)[3]) : "r"(addr))
#define LDM4T(r, addr) \
    asm volatile("ldmatrix.sync.aligned.m8n8.x4.trans.shared.b16 {%0,%1,%2,%3}, [%4];" \
                 : "=r"((r)[0]), "=r"((r)[1]), "=r"((r)[2]), "=r"((r)[3]) : "r"(addr))
#define MMA(d, a, b0, b1) \
    asm volatile("mma.sync.aligned.m16n8k16.row.col.f32.bf16.bf16.f32 " \
                 "{%0,%1,%2,%3}, {%4,%5,%6,%7}, {%8,%9}, {%0,%1,%2,%3};" \
                 : "+f"((d)[0]), "+f"((d)[1]), "+f"((d)[2]), "+f"((d)[3]) \
                 : "r"((a)[0]), "r"((a)[1]), "r"((a)[2]), "r"((a)[3]), "r"(b0), "r"(b1))
// 3-term pair (hh, hl, lh per acc), 2-term pair (hh, hl), 1-term pair (hh)
#define MMA6(de, do_, a_h, a_l, bh, bl) \
    do { \
        MMA(de,  a_h, (bh)[0], (bh)[1]);  MMA(do_, a_h, (bh)[2], (bh)[3]); \
        MMA(de,  a_h, (bl)[0], (bl)[1]);  MMA(do_, a_h, (bl)[2], (bl)[3]); \
        MMA(de,  a_l, (bh)[0], (bh)[1]);  MMA(do_, a_l, (bh)[2], (bh)[3]); \
    } while (0)
#define MMA2(de, do_, a_h, bh) \
    do { \
        MMA(de,  a_h, (bh)[0], (bh)[1]);  MMA(do_, a_h, (bh)[2], (bh)[3]); \
    } while (0)
#define STS2(addr, a, b) \
    asm volatile("st.shared.v2.b32 [%0], {%1, %2};" :: "r"(addr), "r"(a), "r"(b))
#define CPA16(dst, src) \
    asm volatile("cp.async.cg.shared.global [%0], [%1], 16;" :: "r"(dst), "l"(src))
#define CPA_COMMIT() asm volatile("cp.async.commit_group;" ::: "memory")
#define CPA_WAIT1()  asm volatile("cp.async.wait_group 1;" ::: "memory")
#define CPA_WAIT0()  asm volatile("cp.async.wait_group 0;" ::: "memory")

#define SM_XL   34816
#define WBUF_SZ 34816u
#define GEMM_SMEM 104448

// ---------- prep ----------
__global__ void prep_cmrp_kernel(const float* __restrict__ m, const float* __restrict__ s,
                                 const int* __restrict__ rpi, const float* __restrict__ bt) {
    int gi = (blockIdx.x * 256 + threadIdx.x) * 4;
    int w = gi >> 14, i = gi & 16383;
    float4 a = *(const float4*)(m + (size_t)w * 16384 + i);
    float4 c = *(const float4*)(s + (size_t)w * 16384 + i);
    a.x += c.x; a.y += c.y; a.z += c.z; a.w += c.w;
    int4 r = *(const int4*)(rpi + i);
#pragma unroll
    for (int h = 0; h < HEADS; ++h) {
        float4 o = make_float4(a.x + __ldg(bt + r.x * 4 + h), a.y + __ldg(bt + r.y * 4 + h),
                               a.z + __ldg(bt + r.z * 4 + h), a.w + __ldg(bt + r.w * 4 + h));
        *(float4*)(g_cmrp + (((size_t)w * 4 + h) << 14) + i) = o;
    }
}
__global__ void conv_w_kernel(const float* __restrict__ w, int n, int which) {
    int i = blockIdx.x * 256 + threadIdx.x;
    if (i >= n) return;
    int row = i >> 4, c0 = (i & 15) * 8;
    const float* wr = w + row * DIM + c0;
    float4 v0 = *(const float4*)(wr), v1 = *(const float4*)(wr + 4);
    uint4 hv = make_uint4(pk2(v0.x, v0.y), pk2(v0.z, v0.w), pk2(v1.x, v1.y), pk2(v1.z, v1.w));
    uint4 lv = make_uint4(pk2(v0.x - bfh(v0.x), v0.y - bfh(v0.y)),
                          pk2(v0.z - bfh(v0.z), v0.w - bfh(v0.w)),
                          pk2(v1.x - bfh(v1.x), v1.y - bfh(v1.y)),
                          pk2(v1.z - bfh(v1.z), v1.w - bfh(v1.w)));
    if (which == 0) { g_wqkv_h[i] = hv; g_wqkv_l[i] = lv; }
    else            { g_wproj_h[i] = hv; g_wproj_l[i] = lv; }
}

// ---------- GEMM pieces ----------
__device__ __forceinline__ void conv_A(const float* __restrict__ src, uint32_t XH, int tid) {
    for (int i = tid; i < 4096; i += 256) {
        int t = i >> 5, c = (i & 31) * 4;
        float4 v = *(const float4*)(src + t * DIM + c);
        uint32_t o = XH + (uint32_t)(t * PAD + c) * 2u;
        STS2(o, pk2(v.x, v.y), pk2(v.z, v.w));
        STS2(o + SM_XL, pk2(v.x - bfh(v.x), v.y - bfh(v.y)),
             pk2(v.z - bfh(v.z), v.w - bfh(v.w)));
    }
}
__device__ __forceinline__ void fill_A_packed(const uint4* __restrict__ cp, uint32_t XH, int tid) {
    for (int i = tid; i < 4096; i += 256) {
        int t = i >> 5, p2 = i & 31;
        uint4 v = __ldg(cp + i);
        uint32_t o = XH + (uint32_t)(t * 272 + p2 * 8);
        STS2(o, v.x, v.z);
        STS2(o + SM_XL, v.y, v.w);
    }
}
// async-copy one W chunk; lo plane optional (skipped for 1-term chunks)
__device__ __forceinline__ void cpW_async(const uint4* __restrict__ gh,
                                          const uint4* __restrict__ gl,
                                          uint32_t wb, int tid, bool needlo) {
    for (int i = tid; i < 1024; i += 256) {
        int row = i >> 4, c8 = i & 15;
        uint32_t o = wb + (uint32_t)(row * 272 + c8 * 16);
        CPA16(o, gh + i);
        if (needlo) CPA16(o + 17408, gl + i);
    }
}

// MODE 0: qkv (q,k chunks 1-term + hi-only store; v chunks 3-term + hi/lo store)
// MODE 1: proj (3-term, fp32 out + bias)
template <int NCHUNK, int MODE>
__device__ __forceinline__ void gemm_mma(const float* __restrict__ xsrc,
                                         const uint4* __restrict__ wh,
                                         const uint4* __restrict__ wl,
                                         const float* __restrict__ bias,
                                         float* __restrict__ gen_out, int b) {
    extern __shared__ unsigned char sraw[];
    uint32_t XH = smem_u32(sraw);
    int tid = threadIdx.x, wid = tid >> 5, lane = tid & 31;
    if (MODE == 0) conv_A(xsrc, XH, tid);
    else           fill_A_packed((const uint4*)g_ctxp + (size_t)b * 4096, XH, tid);
    __syncthreads();

    int r0 = wid * 16;
    int lr = lane & 15, kh = (lane >> 4) & 1;
    int brow = ((lane >> 4) & 1) * 8 + (lane & 7);
    int bseg = (lane >> 3) & 1;
    uint32_t abase = XH + (uint32_t)((r0 + lr) * PAD + kh * 8) * 2u;
    uint32_t boff = (uint32_t)(brow * 272 + bseg * 16);

    uint32_t ah[8][4], al[8][4];
#pragma unroll
    for (int k = 0; k < 8; ++k) {
        LDM4(ah[k], abase + (uint32_t)(k * 32));
        LDM4(al[k], abase + SM_XL + (uint32_t)(k * 32));
    }
    __syncthreads();

    // needlo per chunk: MODE 1 always; MODE 0 only v chunks (ch >= 4)
    cpW_async(wh, wl, XH, tid, MODE == 1);
    CPA_COMMIT();
    if (NCHUNK > 1) { cpW_async(wh + 1024, wl + 1024, XH + WBUF_SZ, tid, MODE == 1); CPA_COMMIT(); }

    for (int ch = 0; ch < NCHUNK; ++ch) {
        if (ch + 1 < NCHUNK) CPA_WAIT1(); else CPA_WAIT0();
        __syncthreads();
        if (ch + 2 < NCHUNK) {
            cpW_async(wh + (ch + 2) * 1024, wl + (ch + 2) * 1024,
                      XH + (uint32_t)(((ch + 2) % 3) * WBUF_SZ), tid,
                      MODE == 1 || (ch + 2) >= 4);
            CPA_COMMIT();
        }
        uint32_t bbase = XH + (uint32_t)((ch % 3) * WBUF_SZ) + boff;
        bool full3 = (MODE == 1) || (ch >= 4);   // v chunks 3-term; q,k 1-term

        float acc[8][4];
#pragma unroll
        for (int nt = 0; nt < 8; ++nt)
#pragma unroll
            for (int j = 0; j < 4; ++j) acc[nt][j] = 0.f;
#pragma unroll
        for (int k = 0; k < 8; ++k) {
#pragma unroll
            for (int ntp = 0; ntp < 4; ++ntp) {
                uint32_t ba = bbase + (uint32_t)(ntp * 16 * 272 + k * 32);
                uint32_t bh[4];
                LDM4(bh, ba);
                if (full3) {
                    uint32_t bl[4];
                    LDM4(bl, ba + 17408);
                    MMA6(acc[2 * ntp], acc[2 * ntp + 1], ah[k], al[k], bh, bl);
                } else {
                    MMA2(acc[2 * ntp], acc[2 * ntp + 1], ah[k], bh);
                }
            }
        }

        int t0 = r0 + (lane >> 2);
#pragma unroll
        for (int nt = 0; nt < 8; ++nt) {
            int f = ch * 64 + nt * 8 + (lane & 3) * 2;
            float bx = __ldg(bias + f), by = __ldg(bias + f + 1);
            if (MODE == 0) {
                int s = f >> 7, h = (f >> 5) & 3, dpair = (f & 31) >> 1;
                float sc = (s == 0) ? SCALEF : 1.0f;
                uint32_t* ph = (s == 0 ? g_qph : s == 1 ? g_kph : g_vph);
                size_t off = (((size_t)b * HEADS + h) * NTOK + t0) * 16 + dpair;
                float v0 = (acc[nt][0] + bx) * sc, v1 = (acc[nt][1] + by) * sc;
                float v2 = (acc[nt][2] + bx) * sc, v3 = (acc[nt][3] + by) * sc;
                ph[off] = pk2(v0, v1);
                ph[off + 8 * 16] = pk2(v2, v3);
                if (s == 2) {
                    g_vpl[off] = pk2(v0 - bfh(v0), v1 - bfh(v1));
                    g_vpl[off + 8 * 16] = pk2(v2 - bfh(v2), v3 - bfh(v3));
                }
            } else {
                *(float2*)(gen_out + ((size_t)b * NTOK + t0) * DIM + f) =
                    make_float2(acc[nt][0] + bx, acc[nt][1] + by);
                *(float2*)(gen_out + ((size_t)b * NTOK + t0 + 8) * DIM + f) =
                    make_float2(acc[nt][2] + bx, acc[nt][3] + by);
            }
        }
    }
}
__global__ __launch_bounds__(256, 2)
void qkv_mma_kernel(const float* __restrict__ x, const float* __restrict__ b_qkv) {
    gemm_mma<6, 0>(x + (size_t)blockIdx.x * NTOK * DIM, g_wqkv_h, g_wqkv_l, b_qkv,
                   nullptr, blockIdx.x);
}
__global__ __launch_bounds__(256, 2)
void proj_mma_kernel(const float* __restrict__ b_proj, float* __restrict__ out) {
    gemm_mma<2, 1>(nullptr, g_wproj_h, g_wproj_l, b_proj, out, blockIdx.x);
}

// ---------- attention: Q,K hi-only (1-term S), V hi/lo (3-term PV) ----------
#define A_QH 0u
#define A_KH 10240u
#define A_VH 20480u
#define A_VL 30720u
#define ATT_SMEM 40960

__device__ __forceinline__ void cp_plane(uint32_t dst, const uint32_t* __restrict__ src, int tid) {
#pragma unroll
    for (int r = 0; r < 2; ++r) {
        int i = tid + r * 256;
        int t = i >> 2, seg = i & 3;
        CPA16(dst + (uint32_t)(t * 80 + seg * 16), src + (size_t)t * 16 + seg * 4);
    }
}

__global__ __launch_bounds__(256, 2)
void att_mma_kernel() {
    int b = blockIdx.x, h = blockIdx.y;
    extern __shared__ unsigned char sraw[];
    uint32_t sb = smem_u32(sraw);

    int tid = threadIdx.x, lane = tid & 31, wid = tid >> 5;
    size_t pbase = ((size_t)b * HEADS + h) * (NTOK * 16);

    cp_plane(sb + A_QH, g_qph + pbase, tid);
    cp_plane(sb + A_KH, g_kph + pbase, tid);
    cp_plane(sb + A_VH, g_vph + pbase, tid);
    cp_plane(sb + A_VL, g_vpl + pbase, tid);
    CPA_COMMIT();
    CPA_WAIT0();
    __syncthreads();

    int r0 = wid * 16;
    int lr = lane & 15, khf = (lane >> 4) & 1;
    int brow = ((lane >> 4) & 1) * 8 + (lane & 7);
    int bseg = (lane >> 3) & 1;
    uint32_t qa = sb + A_QH + (uint32_t)((r0 + lr) * 80 + khf * 16);
    uint32_t ka = sb + A_KH + (uint32_t)(brow * 80 + bseg * 16);
    int vrow = (lane & 7) + ((lane >> 3) & 1) * 8;
    uint32_t va = sb + A_VH + (uint32_t)(vrow * 80 + ((lane >> 4) & 1) * 16);

    uint32_t ah[2][4];
#pragma unroll
    for (int k = 0; k < 2; ++k) LDM4(ah[k], qa + (uint32_t)(k * 32));

    // ---- S = q k^T, single-term bf16 ----
    float sacc[16][4];
#pragma unroll
    for (int j = 0; j < 16; ++j)
#pragma unroll
        for (int c = 0; c < 4; ++c) sacc[j][c] = 0.f;
#pragma unroll
    for (int ntp = 0; ntp < 8; ++ntp) {
#pragma unroll
        for (int k = 0; k < 2; ++k) {
            uint32_t ba = ka + (uint32_t)(ntp * 16 * 80 + k * 32);
            uint32_t bh[4];
            LDM4(bh, ba);
            MMA(sacc[2 * ntp],     ah[k], bh[0], bh[1]);
            MMA(sacc[2 * ntp + 1], ah[k], bh[2], bh[3]);
        }
    }

    int g = lane >> 2, q2 = (lane & 3) * 2;
    int row0 = r0 + g;
    const float* cm = g_cmrp + (((size_t)(b & (NMASK - 1)) * HEADS + h) << 14)
                    + row0 * NTOK + q2;
#pragma unroll
    for (int j = 0; j < 16; ++j) {
        float2 c0 = *(const float2*)(cm + j * 8);
        float2 c1 = *(const float2*)(cm + 8 * NTOK + j * 8);
        sacc[j][0] += c0.x;  sacc[j][1] += c0.y;
        sacc[j][2] += c1.x;  sacc[j][3] += c1.y;
    }

    float mx0 = -1e30f, mx1 = -1e30f;
#pragma unroll
    for (int j = 0; j < 16; ++j) {
        mx0 = fmaxf(mx0, fmaxf(sacc[j][0], sacc[j][1]));
        mx1 = fmaxf(mx1, fmaxf(sacc[j][2], sacc[j][3]));
    }
    mx0 = fmaxf(mx0, __shfl_xor_sync(0xffffffffu, mx0, 1));
    mx0 = fmaxf(mx0, __shfl_xor_sync(0xffffffffu, mx0, 2));
    mx1 = fmaxf(mx1, __shfl_xor_sync(0xffffffffu, mx1, 1));
    mx1 = fmaxf(mx1, __shfl_xor_sync(0xffffffffu, mx1, 2));
    float s0 = 0.f, s1 = 0.f;
#pragma unroll
    for (int j = 0; j < 16; ++j) {
        sacc[j][0] = __expf(sacc[j][0] - mx0);
        sacc[j][1] = __expf(sacc[j][1] - mx0);
        sacc[j][2] = __expf(sacc[j][2] - mx1);
        sacc[j][3] = __expf(sacc[j][3] - mx1);
        s0 += sacc[j][0] + sacc[j][1];
        s1 += sacc[j][2] + sacc[j][3];
    }
    s0 += __shfl_xor_sync(0xffffffffu, s0, 1);
    s0 += __shfl_xor_sync(0xffffffffu, s0, 2);
    s1 += __shfl_xor_sync(0xffffffffu, s1, 1);
    s1 += __shfl_xor_sync(0xffffffffu, s1, 2);
    float inv0 = 1.0f / s0, inv1 = 1.0f / s1;

    // ---- PV: P hi/lo in-register, V hi/lo (3-term) ----
    float oacc[4][4];
#pragma unroll
    for (int dn = 0; dn < 4; ++dn)
#pragma unroll
        for (int c = 0; c < 4; ++c) oacc[dn][c] = 0.f;
#pragma unroll
    for (int kk = 0; kk < 8; ++kk) {
        float p00 = sacc[2 * kk][0],     p01 = sacc[2 * kk][1];
        float p10 = sacc[2 * kk][2],     p11 = sacc[2 * kk][3];
        float p20 = sacc[2 * kk + 1][0], p21 = sacc[2 * kk + 1][1];
        float p30 = sacc[2 * kk + 1][2], p31 = sacc[2 * kk + 1][3];
        uint32_t aH[4], aL[4];
        aH[0] = pk2(p00, p01); aH[1] = pk2(p10, p11);
        aH[2] = pk2(p20, p21); aH[3] = pk2(p30, p31);
        aL[0] = pk2(p00 - bfh(p00), p01 - bfh(p01));
        aL[1] = pk2(p10 - bfh(p10), p11 - bfh(p11));
        aL[2] = pk2(p20 - bfh(p20), p21 - bfh(p21));
        aL[3] = pk2(p30 - bfh(p30), p31 - bfh(p31));
#pragma unroll
        for (int dnp = 0; dnp < 2; ++dnp) {
            uint32_t ba = va + (uint32_t)(kk * 16 * 80 + dnp * 32);
            uint32_t bh[4], bl[4];
            LDM4T(bh, ba);
            LDM4T(bl, ba + (A_VL - A_VH));
            MMA6(oacc[2 * dnp], oacc[2 * dnp + 1], aH, aL, bh, bl);
        }
    }

    uint2* cp0 = g_ctxp + ((size_t)b * NTOK + row0) * 64 + h * 16 + (lane & 3);
#pragma unroll
    for (int dn = 0; dn < 4; ++dn) {
        float v0 = oacc[dn][0] * inv0, v1 = oacc[dn][1] * inv0;
        cp0[dn * 4] = make_uint2(pk2(v0, v1), pk2(v0 - bfh(v0), v1 - bfh(v1)));
        float v2 = oacc[dn][2] * inv1, v3 = oacc[dn][3] * inv1;
        cp0[8 * 64 + dn * 4] = make_uint2(pk2(v2, v3), pk2(v2 - bfh(v2), v3 - bfh(v3)));
    }
}

// ---------- launch ----------
extern "C" void kernel_launch(void* const* d_in, const int* in_sizes, int n_in,
                              void* d_out, int out_size) {
    const float* x          = (const float*)d_in[0];
    const int*   rpi        = (const int*)d_in[1];
    const float* mask       = (const float*)d_in[2];
    const float* sp_mask    = (const float*)d_in[3];
    const float* w_qkv      = (const float*)d_in[4];
    const float* b_qkv      = (const float*)d_in[5];
    const float* bias_table = (const float*)d_in[6];
    const float* w_proj     = (const float*)d_in[7];
    const float* b_proj     = (const float*)d_in[8];
    float* out = (float*)d_out;

    cudaFuncSetAttribute((const void*)qkv_mma_kernel,
                         cudaFuncAttributeMaxDynamicSharedMemorySize, GEMM_SMEM);
    cudaFuncSetAttribute((const void*)proj_mma_kernel,
                         cudaFuncAttributeMaxDynamicSharedMemorySize, GEMM_SMEM);
    cudaFuncSetAttribute((const void*)att_mma_kernel,
                         cudaFuncAttributeMaxDynamicSharedMemorySize, ATT_SMEM);

    prep_cmrp_kernel<<<4096, 256>>>(mask, sp_mask, rpi, bias_table);
    conv_w_kernel<<<24, 256>>>(w_qkv, 6144, 0);
    conv_w_kernel<<<8, 256>>>(w_proj, 2048, 1);
    qkv_mma_kernel<<<BWIN, 256, GEMM_SMEM>>>(x, b_qkv);
    att_mma_kernel<<<dim3(BWIN, HEADS), 256, ATT_SMEM>>>();
    proj_mma_kernel<<<BWIN, 256, GEMM_SMEM>>>(b_proj, out);
}

// round 16
// speedup vs baseline: 1.2041x; 1.0487x over previous
#include <cuda_runtime.h>
#include <cuda_fp16.h>
#include <stdint.h>

#define DIM   128
#define HEADS 4
#define HD    32
#define NTOK  128
#define BWIN  2048
#define NMASK 256
#define SCALEF 0.1767766952966369f
#define PAD   136

// merged bias plane: mask + sp_mask + rpb per (w,h)
__device__ float g_cmrp[(size_t)NMASK * HEADS * NTOK * NTOK];
// q,k: single fp16 planes; v: fp16 hi+lo
__device__ uint32_t g_qph[(size_t)BWIN * HEADS * NTOK * 16];
__device__ uint32_t g_kph[(size_t)BWIN * HEADS * NTOK * 16];
__device__ uint32_t g_vph[(size_t)BWIN * HEADS * NTOK * 16];
__device__ uint32_t g_vpl[(size_t)BWIN * HEADS * NTOK * 16];
// packed ctx: [b][t][64 dpairs] uint2{hi01, lo01} (fp16)
__device__ uint2 g_ctxp[(size_t)BWIN * NTOK * 64];
__device__ uint4 g_wqkv_h[6144], g_wqkv_l[6144];
__device__ uint4 g_wproj_h[2048], g_wproj_l[2048];

// ---------- helpers ----------
__device__ __forceinline__ uint32_t smem_u32(const void* p) {
    uint32_t a;
    asm("{ .reg .u64 t; cvta.to.shared.u64 t, %1; cvt.u32.u64 %0, t; }" : "=r"(a) : "l"(p));
    return a;
}
__device__ __forceinline__ uint32_t pk2h(float a, float b) {
    __half2 t = __floats2half2_rn(a, b);
    return *reinterpret_cast<uint32_t*>(&t);
}
__device__ __forceinline__ float hfh(float x) {
    return __half2float(__float2half_rn(x));
}
#define LDM4(r, addr) \
    asm volatile("ldmatrix.sync.aligned.m8n8.x4.shared.b16 {%0,%1,%2,%3}, [%4];" \
                 : "=r"((r)[0]), "=r"((r)[1]), "=r"((r)[2]), "=r"((r)[3]) : "r"(addr))
#define LDM4T(r, addr) \
    asm volatile("ldmatrix.sync.aligned.m8n8.x4.trans.shared.b16 {%0,%1,%2,%3}, [%4];" \
                 : "=r"((r)[0]), "=r"((r)[1]), "=r"((r)[2]), "=r"((r)[3]) : "r"(addr))
#define MMA(d, a, b0, b1) \
    asm volatile("mma.sync.aligned.m16n8k16.row.col.f32.f16.f16.f32 " \
                 "{%0,%1,%2,%3}, {%4,%5,%6,%7}, {%8,%9}, {%0,%1,%2,%3};" \
                 : "+f"((d)[0]), "+f"((d)[1]), "+f"((d)[2]), "+f"((d)[3]) \
                 : "r"((a)[0]), "r"((a)[1]), "r"((a)[2]), "r"((a)[3]), "r"(b0), "r"(b1))
#define MMA6(de, do_, a_h, a_l, bh, bl) \
    do { \
        MMA(de,  a_h, (bh)[0], (bh)[1]);  MMA(do_, a_h, (bh)[2], (bh)[3]); \
        MMA(de,  a_h, (bl)[0], (bl)[1]);  MMA(do_, a_h, (bl)[2], (bl)[3]); \
        MMA(de,  a_l, (bh)[0], (bh)[1]);  MMA(do_, a_l, (bh)[2], (bh)[3]); \
    } while (0)
#define MMA4(de, do_, a_h, bh, bl) \
    do { \
        MMA(de,  a_h, (bh)[0], (bh)[1]);  MMA(do_, a_h, (bh)[2], (bh)[3]); \
        MMA(de,  a_h, (bl)[0], (bl)[1]);  MMA(do_, a_h, (bl)[2], (bl)[3]); \
    } while (0)
#define MMA2(de, do_, a_h, bh) \
    do { \
        MMA(de,  a_h, (bh)[0], (bh)[1]);  MMA(do_, a_h, (bh)[2], (bh)[3]); \
    } while (0)
#define STS2(addr, a, b) \
    asm volatile("st.shared.v2.b32 [%0], {%1, %2};" :: "r"(addr), "r"(a), "r"(b))
#define CPA16(dst, src) \
    asm volatile("cp.async.cg.shared.global [%0], [%1], 16;" :: "r"(dst), "l"(src))
#define CPA_COMMIT() asm volatile("cp.async.commit_group;" ::: "memory")
#define CPA_WAIT1()  asm volatile("cp.async.wait_group 1;" ::: "memory")
#define CPA_WAIT0()  asm volatile("cp.async.wait_group 0;" ::: "memory")

#define SM_XL   34816
#define WBUF_SZ 34816u
#define GEMM_SMEM 104448

// ---------- prep ----------
__global__ void prep_cmrp_kernel(const float* __restrict__ m, const float* __restrict__ s,
                                 const int* __restrict__ rpi, const float* __restrict__ bt) {
    int gi = (blockIdx.x * 256 + threadIdx.x) * 4;
    int w = gi >> 14, i = gi & 16383;
    float4 a = *(const float4*)(m + (size_t)w * 16384 + i);
    float4 c = *(const float4*)(s + (size_t)w * 16384 + i);
    a.x += c.x; a.y += c.y; a.z += c.z; a.w += c.w;
    int4 r = *(const int4*)(rpi + i);
#pragma unroll
    for (int h = 0; h < HEADS; ++h) {
        float4 o = make_float4(a.x + __ldg(bt + r.x * 4 + h), a.y + __ldg(bt + r.y * 4 + h),
                               a.z + __ldg(bt + r.z * 4 + h), a.w + __ldg(bt + r.w * 4 + h));
        *(float4*)(g_cmrp + (((size_t)w * 4 + h) << 14) + i) = o;
    }
}
__global__ void conv_w_kernel(const float* __restrict__ w, int n, int which) {
    int i = blockIdx.x * 256 + threadIdx.x;
    if (i >= n) return;
    int row = i >> 4, c0 = (i & 15) * 8;
    const float* wr = w + row * DIM + c0;
    float4 v0 = *(const float4*)(wr), v1 = *(const float4*)(wr + 4);
    uint4 hv = make_uint4(pk2h(v0.x, v0.y), pk2h(v0.z, v0.w), pk2h(v1.x, v1.y), pk2h(v1.z, v1.w));
    uint4 lv = make_uint4(pk2h(v0.x - hfh(v0.x), v0.y - hfh(v0.y)),
                          pk2h(v0.z - hfh(v0.z), v0.w - hfh(v0.w)),
                          pk2h(v1.x - hfh(v1.x), v1.y - hfh(v1.y)),
                          pk2h(v1.z - hfh(v1.z), v1.w - hfh(v1.w)));
    if (which == 0) { g_wqkv_h[i] = hv; g_wqkv_l[i] = lv; }
    else            { g_wproj_h[i] = hv; g_wproj_l[i] = lv; }
}

// ---------- GEMM pieces ----------
__device__ __forceinline__ void conv_A(const float* __restrict__ src, uint32_t XH, int tid) {
    for (int i = tid; i < 4096; i += 256) {
        int t = i >> 5, c = (i & 31) * 4;
        float4 v = *(const float4*)(src + t * DIM + c);
        uint32_t o = XH + (uint32_t)(t * PAD + c) * 2u;
        STS2(o, pk2h(v.x, v.y), pk2h(v.z, v.w));
        STS2(o + SM_XL, pk2h(v.x - hfh(v.x), v.y - hfh(v.y)),
             pk2h(v.z - hfh(v.z), v.w - hfh(v.w)));
    }
}
__device__ __forceinline__ void fill_A_packed(const uint4* __restrict__ cp, uint32_t XH, int tid) {
    for (int i = tid; i < 4096; i += 256) {
        int t = i >> 5, p2 = i & 31;
        uint4 v = __ldg(cp + i);
        uint32_t o = XH + (uint32_t)(t * 272 + p2 * 8);
        STS2(o, v.x, v.z);
        STS2(o + SM_XL, v.y, v.w);
    }
}
__device__ __forceinline__ void cpW_async(const uint4* __restrict__ gh,
                                          const uint4* __restrict__ gl,
                                          uint32_t wb, int tid, bool needlo) {
    for (int i = tid; i < 1024; i += 256) {
        int row = i >> 4, c8 = i & 15;
        uint32_t o = wb + (uint32_t)(row * 272 + c8 * 16);
        CPA16(o, gh + i);
        if (needlo) CPA16(o + 17408, gl + i);
    }
}

// MODE 0: qkv (q,k chunks 1-term + single-fp16 store; v chunks 3-term + hi/lo store)
// MODE 1: proj (3-term, fp32 out + bias)
template <int NCHUNK, int MODE>
__device__ __forceinline__ void gemm_mma(const float* __restrict__ xsrc,
                                         const uint4* __restrict__ wh,
                                         const uint4* __restrict__ wl,
                                         const float* __restrict__ bias,
                                         float* __restrict__ gen_out, int b) {
    extern __shared__ unsigned char sraw[];
    uint32_t XH = smem_u32(sraw);
    int tid = threadIdx.x, wid = tid >> 5, lane = tid & 31;
    if (MODE == 0) conv_A(xsrc, XH, tid);
    else           fill_A_packed((const uint4*)g_ctxp + (size_t)b * 4096, XH, tid);
    __syncthreads();

    int r0 = wid * 16;
    int lr = lane & 15, kh = (lane >> 4) & 1;
    int brow = ((lane >> 4) & 1) * 8 + (lane & 7);
    int bseg = (lane >> 3) & 1;
    uint32_t abase = XH + (uint32_t)((r0 + lr) * PAD + kh * 8) * 2u;
    uint32_t boff = (uint32_t)(brow * 272 + bseg * 16);

    uint32_t ah[8][4], al[8][4];
#pragma unroll
    for (int k = 0; k < 8; ++k) {
        LDM4(ah[k], abase + (uint32_t)(k * 32));
        LDM4(al[k], abase + SM_XL + (uint32_t)(k * 32));
    }
    __syncthreads();

    cpW_async(wh, wl, XH, tid, MODE == 1);
    CPA_COMMIT();
    if (NCHUNK > 1) { cpW_async(wh + 1024, wl + 1024, XH + WBUF_SZ, tid, MODE == 1); CPA_COMMIT(); }

    for (int ch = 0; ch < NCHUNK; ++ch) {
        if (ch + 1 < NCHUNK) CPA_WAIT1(); else CPA_WAIT0();
        __syncthreads();
        if (ch + 2 < NCHUNK) {
            cpW_async(wh + (ch + 2) * 1024, wl + (ch + 2) * 1024,
                      XH + (uint32_t)(((ch + 2) % 3) * WBUF_SZ), tid,
                      MODE == 1 || (ch + 2) >= 4);
            CPA_COMMIT();
        }
        uint32_t bbase = XH + (uint32_t)((ch % 3) * WBUF_SZ) + boff;
        bool full3 = (MODE == 1) || (ch >= 4);

        float acc[8][4];
#pragma unroll
        for (int nt = 0; nt < 8; ++nt)
#pragma unroll
            for (int j = 0; j < 4; ++j) acc[nt][j] = 0.f;
#pragma unroll
        for (int k = 0; k < 8; ++k) {
#pragma unroll
            for (int ntp = 0; ntp < 4; ++ntp) {
                uint32_t ba = bbase + (uint32_t)(ntp * 16 * 272 + k * 32);
                uint32_t bh[4];
                LDM4(bh, ba);
                if (full3) {
                    uint32_t bl[4];
                    LDM4(bl, ba + 17408);
                    MMA6(acc[2 * ntp], acc[2 * ntp + 1], ah[k], al[k], bh, bl);
                } else {
                    MMA2(acc[2 * ntp], acc[2 * ntp + 1], ah[k], bh);
                }
            }
        }

        int t0 = r0 + (lane >> 2);
#pragma unroll
        for (int nt = 0; nt < 8; ++nt) {
            int f = ch * 64 + nt * 8 + (lane & 3) * 2;
            float bx = __ldg(bias + f), by = __ldg(bias + f + 1);
            if (MODE == 0) {
                int s = f >> 7, h = (f >> 5) & 3, dpair = (f & 31) >> 1;
                float sc = (s == 0) ? SCALEF : 1.0f;
                uint32_t* ph = (s == 0 ? g_qph : s == 1 ? g_kph : g_vph);
                size_t off = (((size_t)b * HEADS + h) * NTOK + t0) * 16 + dpair;
                float v0 = (acc[nt][0] + bx) * sc, v1 = (acc[nt][1] + by) * sc;
                float v2 = (acc[nt][2] + bx) * sc, v3 = (acc[nt][3] + by) * sc;
                ph[off] = pk2h(v0, v1);
                ph[off + 8 * 16] = pk2h(v2, v3);
                if (s == 2) {
                    g_vpl[off] = pk2h(v0 - hfh(v0), v1 - hfh(v1));
                    g_vpl[off + 8 * 16] = pk2h(v2 - hfh(v2), v3 - hfh(v3));
                }
            } else {
                *(float2*)(gen_out + ((size_t)b * NTOK + t0) * DIM + f) =
                    make_float2(acc[nt][0] + bx, acc[nt][1] + by);
                *(float2*)(gen_out + ((size_t)b * NTOK + t0 + 8) * DIM + f) =
                    make_float2(acc[nt][2] + bx, acc[nt][3] + by);
            }
        }
    }
}
__global__ __launch_bounds__(256, 2)
void qkv_mma_kernel(const float* __restrict__ x, const float* __restrict__ b_qkv) {
    gemm_mma<6, 0>(x + (size_t)blockIdx.x * NTOK * DIM, g_wqkv_h, g_wqkv_l, b_qkv,
                   nullptr, blockIdx.x);
}
__global__ __launch_bounds__(256, 2)
void proj_mma_kernel(const float* __restrict__ b_proj, float* __restrict__ out) {
    gemm_mma<2, 1>(nullptr, g_wproj_h, g_wproj_l, b_proj, out, blockIdx.x);
}

// ---------- attention: Q,K single fp16 (1-term S), P single fp16 + V hi/lo (2-term PV) ----------
#define A_QH 0u
#define A_KH 10240u
#define A_VH 20480u
#define A_VL 30720u
#define ATT_SMEM 40960

__device__ __forceinline__ void cp_plane(uint32_t dst, const uint32_t* __restrict__ src, int tid) {
#pragma unroll
    for (int r = 0; r < 2; ++r) {
        int i = tid + r * 256;
        int t = i >> 2, seg = i & 3;
        CPA16(dst + (uint32_t)(t * 80 + seg * 16), src + (size_t)t * 16 + seg * 4);
    }
}

__global__ __launch_bounds__(256, 2)
void att_mma_kernel() {
    int b = blockIdx.x, h = blockIdx.y;
    extern __shared__ unsigned char sraw[];
    uint32_t sb = smem_u32(sraw);

    int tid = threadIdx.x, lane = tid & 31, wid = tid >> 5;
    size_t pbase = ((size_t)b * HEADS + h) * (NTOK * 16);

    cp_plane(sb + A_QH, g_qph + pbase, tid);
    cp_plane(sb + A_KH, g_kph + pbase, tid);
    cp_plane(sb + A_VH, g_vph + pbase, tid);
    cp_plane(sb + A_VL, g_vpl + pbase, tid);
    CPA_COMMIT();
    CPA_WAIT0();
    __syncthreads();

    int r0 = wid * 16;
    int lr = lane & 15, khf = (lane >> 4) & 1;
    int brow = ((lane >> 4) & 1) * 8 + (lane & 7);
    int bseg = (lane >> 3) & 1;
    uint32_t qa = sb + A_QH + (uint32_t)((r0 + lr) * 80 + khf * 16);
    uint32_t ka = sb + A_KH + (uint32_t)(brow * 80 + bseg * 16);
    int vrow = (lane & 7) + ((lane >> 3) & 1) * 8;
    uint32_t va = sb + A_VH + (uint32_t)(vrow * 80 + ((lane >> 4) & 1) * 16);

    uint32_t ah[2][4];
#pragma unroll
    for (int k = 0; k < 2; ++k) LDM4(ah[k], qa + (uint32_t)(k * 32));

    float sacc[16][4];
#pragma unroll
    for (int j = 0; j < 16; ++j)
#pragma unroll
        for (int c = 0; c < 4; ++c) sacc[j][c] = 0.f;
#pragma unroll
    for (int ntp = 0; ntp < 8; ++ntp) {
#pragma unroll
        for (int k = 0; k < 2; ++k) {
            uint32_t ba = ka + (uint32_t)(ntp * 16 * 80 + k * 32);
            uint32_t bh[4];
            LDM4(bh, ba);
            MMA(sacc[2 * ntp],     ah[k], bh[0], bh[1]);
            MMA(sacc[2 * ntp + 1], ah[k], bh[2], bh[3]);
        }
    }

    int g = lane >> 2, q2 = (lane & 3) * 2;
    int row0 = r0 + g;
    const float* cm = g_cmrp + (((size_t)(b & (NMASK - 1)) * HEADS + h) << 14)
                    + row0 * NTOK + q2;
#pragma unroll
    for (int j = 0; j < 16; ++j) {
        float2 c0 = *(const float2*)(cm + j * 8);
        float2 c1 = *(const float2*)(cm + 8 * NTOK + j * 8);
        sacc[j][0] += c0.x;  sacc[j][1] += c0.y;
        sacc[j][2] += c1.x;  sacc[j][3] += c1.y;
    }

    float mx0 = -1e30f, mx1 = -1e30f;
#pragma unroll
    for (int j = 0; j < 16; ++j) {
        mx0 = fmaxf(mx0, fmaxf(sacc[j][0], sacc[j][1]));
        mx1 = fmaxf(mx1, fmaxf(sacc[j][2], sacc[j][3]));
    }
    mx0 = fmaxf(mx0, __shfl_xor_sync(0xffffffffu, mx0, 1));
    mx0 = fmaxf(mx0, __shfl_xor_sync(0xffffffffu, mx0, 2));
    mx1 = fmaxf(mx1, __shfl_xor_sync(0xffffffffu, mx1, 1));
    mx1 = fmaxf(mx1, __shfl_xor_sync(0xffffffffu, mx1, 2));
    float s0 = 0.f, s1 = 0.f;
#pragma unroll
    for (int j = 0; j < 16; ++j) {
        sacc[j][0] = __expf(sacc[j][0] - mx0);
        sacc[j][1] = __expf(sacc[j][1] - mx0);
        sacc[j][2] = __expf(sacc[j][2] - mx1);
        sacc[j][3] = __expf(sacc[j][3] - mx1);
        s0 += sacc[j][0] + sacc[j][1];
        s1 += sacc[j][2] + sacc[j][3];
    }
    s0 += __shfl_xor_sync(0xffffffffu, s0, 1);
    s0 += __shfl_xor_sync(0xffffffffu, s0, 2);
    s1 += __shfl_xor_sync(0xffffffffu, s1, 1);
    s1 += __shfl_xor_sync(0xffffffffu, s1, 2);
    float inv0 = 1.0f / s0, inv1 = 1.0f / s1;

    // ---- PV: P single fp16 in-register, V hi/lo (2-term) ----
    float oacc[4][4];
#pragma unroll
    for (int dn = 0; dn < 4; ++dn)
#pragma unroll
        for (int c = 0; c < 4; ++c) oacc[dn][c] = 0.f;
#pragma unroll
    for (int kk = 0; kk < 8; ++kk) {
        uint32_t aH[4];
        aH[0] = pk2h(sacc[2 * kk][0],     sacc[2 * kk][1]);
        aH[1] = pk2h(sacc[2 * kk][2],     sacc[2 * kk][3]);
        aH[2] = pk2h(sacc[2 * kk + 1][0], sacc[2 * kk + 1][1]);
        aH[3] = pk2h(sacc[2 * kk + 1][2], sacc[2 * kk + 1][3]);
#pragma unroll
        for (int dnp = 0; dnp < 2; ++dnp) {
            uint32_t ba = va + (uint32_t)(kk * 16 * 80 + dnp * 32);
            uint32_t bh[4], bl[4];
            LDM4T(bh, ba);
            LDM4T(bl, ba + (A_VL - A_VH));
            MMA4(oacc[2 * dnp], oacc[2 * dnp + 1], aH, bh, bl);
        }
    }

    uint2* cp0 = g_ctxp + ((size_t)b * NTOK + row0) * 64 + h * 16 + (lane & 3);
#pragma unroll
    for (int dn = 0; dn < 4; ++dn) {
        float v0 = oacc[dn][0] * inv0, v1 = oacc[dn][1] * inv0;
        cp0[dn * 4] = make_uint2(pk2h(v0, v1), pk2h(v0 - hfh(v0), v1 - hfh(v1)));
        float v2 = oacc[dn][2] * inv1, v3 = oacc[dn][3] * inv1;
        cp0[8 * 64 + dn * 4] = make_uint2(pk2h(v2, v3), pk2h(v2 - hfh(v2), v3 - hfh(v3)));
    }
}

// ---------- launch ----------
extern "C" void kernel_launch(void* const* d_in, const int* in_sizes, int n_in,
                              void* d_out, int out_size) {
    const float* x          = (const float*)d_in[0];
    const int*   rpi        = (const int*)d_in[1];
    const float* mask       = (const float*)d_in[2];
    const float* sp_mask    = (const float*)d_in[3];
    const float* w_qkv      = (const float*)d_in[4];
    const float* b_qkv      = (const float*)d_in[5];
    const float* bias_table = (const float*)d_in[6];
    const float* w_proj     = (const float*)d_in[7];
    const float* b_proj     = (const float*)d_in[8];
    float* out = (float*)d_out;

    cudaFuncSetAttribute((const void*)qkv_mma_kernel,
                         cudaFuncAttributeMaxDynamicSharedMemorySize, GEMM_SMEM);
    cudaFuncSetAttribute((const void*)proj_mma_kernel,
                         cudaFuncAttributeMaxDynamicSharedMemorySize, GEMM_SMEM);
    cudaFuncSetAttribute((const void*)att_mma_kernel,
                         cudaFuncAttributeMaxDynamicSharedMemorySize, ATT_SMEM);

    prep_cmrp_kernel<<<4096, 256>>>(mask, sp_mask, rpi, bias_table);
    conv_w_kernel<<<24, 256>>>(w_qkv, 6144, 0);
    conv_w_kernel<<<8, 256>>>(w_proj, 2048, 1);
    qkv_mma_kernel<<<BWIN, 256, GEMM_SMEM>>>(x, b_qkv);
    att_mma_kernel<<<dim3(BWIN, HEADS), 256, ATT_SMEM>>>();
    proj_mma_kernel<<<BWIN, 256, GEMM_SMEM>>>(b_proj, out);
}

// round 17
// speedup vs baseline: 1.2147x; 1.0088x over previous
#include <cuda_runtime.h>
#include <cuda_fp16.h>
#include <stdint.h>

#define DIM   128
#define HEADS 4
#define HD    32
#define NTOK  128
#define BWIN  2048
#define NMASK 256
#define SCALEF 0.1767766952966369f
#define PAD   136

// merged bias plane: mask + sp_mask + rpb per (w,h)
__device__ float g_cmrp[(size_t)NMASK * HEADS * NTOK * NTOK];
// q,k: single fp16 planes; v: fp16 hi+lo
__device__ uint32_t g_qph[(size_t)BWIN * HEADS * NTOK * 16];
__device__ uint32_t g_kph[(size_t)BWIN * HEADS * NTOK * 16];
__device__ uint32_t g_vph[(size_t)BWIN * HEADS * NTOK * 16];
__device__ uint32_t g_vpl[(size_t)BWIN * HEADS * NTOK * 16];
// ctx: single fp16, [b][t][64 dpairs]
__device__ uint32_t g_ctxh[(size_t)BWIN * NTOK * 64];
__device__ uint4 g_wqkv_h[6144], g_wqkv_l[6144];
__device__ uint4 g_wproj_h[2048], g_wproj_l[2048];

// ---------- helpers ----------
__device__ __forceinline__ uint32_t smem_u32(const void* p) {
    uint32_t a;
    asm("{ .reg .u64 t; cvta.to.shared.u64 t, %1; cvt.u32.u64 %0, t; }" : "=r"(a) : "l"(p));
    return a;
}
__device__ __forceinline__ uint32_t pk2h(float a, float b) {
    __half2 t = __floats2half2_rn(a, b);
    return *reinterpret_cast<uint32_t*>(&t);
}
__device__ __forceinline__ float hfh(float x) {
    return __half2float(__float2half_rn(x));
}
#define LDM4(r, addr) \
    asm volatile("ldmatrix.sync.aligned.m8n8.x4.shared.b16 {%0,%1,%2,%3}, [%4];" \
                 : "=r"((r)[0]), "=r"((r)[1]), "=r"((r)[2]), "=r"((r)[3]) : "r"(addr))
#define LDM4T(r, addr) \
    asm volatile("ldmatrix.sync.aligned.m8n8.x4.trans.shared.b16 {%0,%1,%2,%3}, [%4];" \
                 : "=r"((r)[0]), "=r"((r)[1]), "=r"((r)[2]), "=r"((r)[3]) : "r"(addr))
#define MMA(d, a, b0, b1) \
    asm volatile("mma.sync.aligned.m16n8k16.row.col.f32.f16.f16.f32 " \
                 "{%0,%1,%2,%3}, {%4,%5,%6,%7}, {%8,%9}, {%0,%1,%2,%3};" \
                 : "+f"((d)[0]), "+f"((d)[1]), "+f"((d)[2]), "+f"((d)[3]) \
                 : "r"((a)[0]), "r"((a)[1]), "r"((a)[2]), "r"((a)[3]), "r"(b0), "r"(b1))
#define MMA4(de, do_, a_h, bh, bl) \
    do { \
        MMA(de,  a_h, (bh)[0], (bh)[1]);  MMA(do_, a_h, (bh)[2], (bh)[3]); \
        MMA(de,  a_h, (bl)[0], (bl)[1]);  MMA(do_, a_h, (bl)[2], (bl)[3]); \
    } while (0)
#define MMA2(de, do_, a_h, bh) \
    do { \
        MMA(de,  a_h, (bh)[0], (bh)[1]);  MMA(do_, a_h, (bh)[2], (bh)[3]); \
    } while (0)
#define STS2(addr, a, b) \
    asm volatile("st.shared.v2.b32 [%0], {%1, %2};" :: "r"(addr), "r"(a), "r"(b))
#define STS4(addr, v) \
    asm volatile("st.shared.v4.b32 [%0], {%1,%2,%3,%4};" \
                 :: "r"(addr), "r"((v).x), "r"((v).y), "r"((v).z), "r"((v).w))
#define CPA16(dst, src) \
    asm volatile("cp.async.cg.shared.global [%0], [%1], 16;" :: "r"(dst), "l"(src))
#define CPA_COMMIT() asm volatile("cp.async.commit_group;" ::: "memory")
#define CPA_WAIT1()  asm volatile("cp.async.wait_group 1;" ::: "memory")
#define CPA_WAIT0()  asm volatile("cp.async.wait_group 0;" ::: "memory")

#define WBUF_SZ 34816u
#define GEMM_SMEM 104448

// ---------- prep ----------
__global__ void prep_cmrp_kernel(const float* __restrict__ m, const float* __restrict__ s,
                                 const int* __restrict__ rpi, const float* __restrict__ bt) {
    int gi = (blockIdx.x * 256 + threadIdx.x) * 4;
    int w = gi >> 14, i = gi & 16383;
    float4 a = *(const float4*)(m + (size_t)w * 16384 + i);
    float4 c = *(const float4*)(s + (size_t)w * 16384 + i);
    a.x += c.x; a.y += c.y; a.z += c.z; a.w += c.w;
    int4 r = *(const int4*)(rpi + i);
#pragma unroll
    for (int h = 0; h < HEADS; ++h) {
        float4 o = make_float4(a.x + __ldg(bt + r.x * 4 + h), a.y + __ldg(bt + r.y * 4 + h),
                               a.z + __ldg(bt + r.z * 4 + h), a.w + __ldg(bt + r.w * 4 + h));
        *(float4*)(g_cmrp + (((size_t)w * 4 + h) << 14) + i) = o;
    }
}
__global__ void conv_w_kernel(const float* __restrict__ w, int n, int which) {
    int i = blockIdx.x * 256 + threadIdx.x;
    if (i >= n) return;
    int row = i >> 4, c0 = (i & 15) * 8;
    const float* wr = w + row * DIM + c0;
    float4 v0 = *(const float4*)(wr), v1 = *(const float4*)(wr + 4);
    uint4 hv = make_uint4(pk2h(v0.x, v0.y), pk2h(v0.z, v0.w), pk2h(v1.x, v1.y), pk2h(v1.z, v1.w));
    uint4 lv = make_uint4(pk2h(v0.x - hfh(v0.x), v0.y - hfh(v0.y)),
                          pk2h(v0.z - hfh(v0.z), v0.w - hfh(v0.w)),
                          pk2h(v1.x - hfh(v1.x), v1.y - hfh(v1.y)),
                          pk2h(v1.z - hfh(v1.z), v1.w - hfh(v1.w)));
    if (which == 0) { g_wqkv_h[i] = hv; g_wqkv_l[i] = lv; }
    else            { g_wproj_h[i] = hv; g_wproj_l[i] = lv; }
}

// ---------- GEMM pieces ----------
// x -> single fp16 plane (hi only)
__device__ __forceinline__ void conv_A(const float* __restrict__ src, uint32_t XH, int tid) {
    for (int i = tid; i < 4096; i += 256) {
        int t = i >> 5, c = (i & 31) * 4;
        float4 v = *(const float4*)(src + t * DIM + c);
        uint32_t o = XH + (uint32_t)(t * PAD + c) * 2u;
        STS2(o, pk2h(v.x, v.y), pk2h(v.z, v.w));
    }
}
// packed fp16 ctx (hi only) -> smem plane
__device__ __forceinline__ void fill_A_packed(const uint4* __restrict__ cp, uint32_t XH, int tid) {
    for (int i = tid; i < 2048; i += 256) {
        int t = i >> 4, p4 = i & 15;
        uint4 v = __ldg(cp + i);
        STS4(XH + (uint32_t)(t * 272 + p4 * 16), v);
    }
}
__device__ __forceinline__ void cpW_async(const uint4* __restrict__ gh,
                                          const uint4* __restrict__ gl,
                                          uint32_t wb, int tid, bool needlo) {
    for (int i = tid; i < 1024; i += 256) {
        int row = i >> 4, c8 = i & 15;
        uint32_t o = wb + (uint32_t)(row * 272 + c8 * 16);
        CPA16(o, gh + i);
        if (needlo) CPA16(o + 17408, gl + i);
    }
}

// MODE 0: qkv (q,k chunks 1-term; v chunks 2-term + hi/lo store)
// MODE 1: proj (2-term, fp32 out + bias)
template <int NCHUNK, int MODE>
__device__ __forceinline__ void gemm_mma(const float* __restrict__ xsrc,
                                         const uint4* __restrict__ wh,
                                         const uint4* __restrict__ wl,
                                         const float* __restrict__ bias,
                                         float* __restrict__ gen_out, int b) {
    extern __shared__ unsigned char sraw[];
    uint32_t XH = smem_u32(sraw);
    int tid = threadIdx.x, wid = tid >> 5, lane = tid & 31;
    if (MODE == 0) conv_A(xsrc, XH, tid);
    else           fill_A_packed((const uint4*)g_ctxh + (size_t)b * 2048, XH, tid);
    __syncthreads();

    int r0 = wid * 16;
    int lr = lane & 15, kh = (lane >> 4) & 1;
    int brow = ((lane >> 4) & 1) * 8 + (lane & 7);
    int bseg = (lane >> 3) & 1;
    uint32_t abase = XH + (uint32_t)((r0 + lr) * PAD + kh * 8) * 2u;
    uint32_t boff = (uint32_t)(brow * 272 + bseg * 16);

    uint32_t ah[8][4];
#pragma unroll
    for (int k = 0; k < 8; ++k) LDM4(ah[k], abase + (uint32_t)(k * 32));
    __syncthreads();

    cpW_async(wh, wl, XH, tid, MODE == 1);
    CPA_COMMIT();
    if (NCHUNK > 1) { cpW_async(wh + 1024, wl + 1024, XH + WBUF_SZ, tid, MODE == 1); CPA_COMMIT(); }

    for (int ch = 0; ch < NCHUNK; ++ch) {
        if (ch + 1 < NCHUNK) CPA_WAIT1(); else CPA_WAIT0();
        __syncthreads();
        if (ch + 2 < NCHUNK) {
            cpW_async(wh + (ch + 2) * 1024, wl + (ch + 2) * 1024,
                      XH + (uint32_t)(((ch + 2) % 3) * WBUF_SZ), tid,
                      MODE == 1 || (ch + 2) >= 4);
            CPA_COMMIT();
        }
        uint32_t bbase = XH + (uint32_t)((ch % 3) * WBUF_SZ) + boff;
        bool two = (MODE == 1) || (ch >= 4);   // v / proj: 2-term; q,k: 1-term

        float acc[8][4];
#pragma unroll
        for (int nt = 0; nt < 8; ++nt)
#pragma unroll
            for (int j = 0; j < 4; ++j) acc[nt][j] = 0.f;
#pragma unroll
        for (int k = 0; k < 8; ++k) {
#pragma unroll
            for (int ntp = 0; ntp < 4; ++ntp) {
                uint32_t ba = bbase + (uint32_t)(ntp * 16 * 272 + k * 32);
                uint32_t bh[4];
                LDM4(bh, ba);
                if (two) {
                    uint32_t bl[4];
                    LDM4(bl, ba + 17408);
                    MMA4(acc[2 * ntp], acc[2 * ntp + 1], ah[k], bh, bl);
                } else {
                    MMA2(acc[2 * ntp], acc[2 * ntp + 1], ah[k], bh);
                }
            }
        }

        int t0 = r0 + (lane >> 2);
#pragma unroll
        for (int nt = 0; nt < 8; ++nt) {
            int f = ch * 64 + nt * 8 + (lane & 3) * 2;
            float bx = __ldg(bias + f), by = __ldg(bias + f + 1);
            if (MODE == 0) {
                int s = f >> 7, h = (f >> 5) & 3, dpair = (f & 31) >> 1;
                float sc = (s == 0) ? SCALEF : 1.0f;
                uint32_t* ph = (s == 0 ? g_qph : s == 1 ? g_kph : g_vph);
                size_t off = (((size_t)b * HEADS + h) * NTOK + t0) * 16 + dpair;
                float v0 = (acc[nt][0] + bx) * sc, v1 = (acc[nt][1] + by) * sc;
                float v2 = (acc[nt][2] + bx) * sc, v3 = (acc[nt][3] + by) * sc;
                ph[off] = pk2h(v0, v1);
                ph[off + 8 * 16] = pk2h(v2, v3);
                if (s == 2) {
                    g_vpl[off] = pk2h(v0 - hfh(v0), v1 - hfh(v1));
                    g_vpl[off + 8 * 16] = pk2h(v2 - hfh(v2), v3 - hfh(v3));
                }
            } else {
                *(float2*)(gen_out + ((size_t)b * NTOK + t0) * DIM + f) =
                    make_float2(acc[nt][0] + bx, acc[nt][1] + by);
                *(float2*)(gen_out + ((size_t)b * NTOK + t0 + 8) * DIM + f) =
                    make_float2(acc[nt][2] + bx, acc[nt][3] + by);
            }
        }
    }
}
__global__ __launch_bounds__(256, 2)
void qkv_mma_kernel(const float* __restrict__ x, const float* __restrict__ b_qkv) {
    gemm_mma<6, 0>(x + (size_t)blockIdx.x * NTOK * DIM, g_wqkv_h, g_wqkv_l, b_qkv,
                   nullptr, blockIdx.x);
}
__global__ __launch_bounds__(256, 2)
void proj_mma_kernel(const float* __restrict__ b_proj, float* __restrict__ out) {
    gemm_mma<2, 1>(nullptr, g_wproj_h, g_wproj_l, b_proj, out, blockIdx.x);
}

// ---------- attention: Q,K single fp16 (1-term S), P single fp16 + V hi/lo (2-term PV) ----------
#define A_QH 0u
#define A_KH 10240u
#define A_VH 20480u
#define A_VL 30720u
#define ATT_SMEM 40960

__device__ __forceinline__ void cp_plane(uint32_t dst, const uint32_t* __restrict__ src, int tid) {
#pragma unroll
    for (int r = 0; r < 2; ++r) {
        int i = tid + r * 256;
        int t = i >> 2, seg = i & 3;
        CPA16(dst + (uint32_t)(t * 80 + seg * 16), src + (size_t)t * 16 + seg * 4);
    }
}

__global__ __launch_bounds__(256, 2)
void att_mma_kernel() {
    int b = blockIdx.x, h = blockIdx.y;
    extern __shared__ unsigned char sraw[];
    uint32_t sb = smem_u32(sraw);

    int tid = threadIdx.x, lane = tid & 31, wid = tid >> 5;
    size_t pbase = ((size_t)b * HEADS + h) * (NTOK * 16);

    cp_plane(sb + A_QH, g_qph + pbase, tid);
    cp_plane(sb + A_KH, g_kph + pbase, tid);
    cp_plane(sb + A_VH, g_vph + pbase, tid);
    cp_plane(sb + A_VL, g_vpl + pbase, tid);
    CPA_COMMIT();
    CPA_WAIT0();
    __syncthreads();

    int r0 = wid * 16;
    int lr = lane & 15, khf = (lane >> 4) & 1;
    int brow = ((lane >> 4) & 1) * 8 + (lane & 7);
    int bseg = (lane >> 3) & 1;
    uint32_t qa = sb + A_QH + (uint32_t)((r0 + lr) * 80 + khf * 16);
    uint32_t ka = sb + A_KH + (uint32_t)(brow * 80 + bseg * 16);
    int vrow = (lane & 7) + ((lane >> 3) & 1) * 8;
    uint32_t va = sb + A_VH + (uint32_t)(vrow * 80 + ((lane >> 4) & 1) * 16);

    uint32_t ah[2][4];
#pragma unroll
    for (int k = 0; k < 2; ++k) LDM4(ah[k], qa + (uint32_t)(k * 32));

    float sacc[16][4];
#pragma unroll
    for (int j = 0; j < 16; ++j)
#pragma unroll
        for (int c = 0; c < 4; ++c) sacc[j][c] = 0.f;
#pragma unroll
    for (int ntp = 0; ntp < 8; ++ntp) {
#pragma unroll
        for (int k = 0; k < 2; ++k) {
            uint32_t ba = ka + (uint32_t)(ntp * 16 * 80 + k * 32);
            uint32_t bh[4];
            LDM4(bh, ba);
            MMA(sacc[2 * ntp],     ah[k], bh[0], bh[1]);
            MMA(sacc[2 * ntp + 1], ah[k], bh[2], bh[3]);
        }
    }

    int g = lane >> 2, q2 = (lane & 3) * 2;
    int row0 = r0 + g;
    const float* cm = g_cmrp + (((size_t)(b & (NMASK - 1)) * HEADS + h) << 14)
                    + row0 * NTOK + q2;
#pragma unroll
    for (int j = 0; j < 16; ++j) {
        float2 c0 = *(const float2*)(cm + j * 8);
        float2 c1 = *(const float2*)(cm + 8 * NTOK + j * 8);
        sacc[j][0] += c0.x;  sacc[j][1] += c0.y;
        sacc[j][2] += c1.x;  sacc[j][3] += c1.y;
    }

    float mx0 = -1e30f, mx1 = -1e30f;
#pragma unroll
    for (int j = 0; j < 16; ++j) {
        mx0 = fmaxf(mx0, fmaxf(sacc[j][0], sacc[j][1]));
        mx1 = fmaxf(mx1, fmaxf(sacc[j][2], sacc[j][3]));
    }
    mx0 = fmaxf(mx0, __shfl_xor_sync(0xffffffffu, mx0, 1));
    mx0 = fmaxf(mx0, __shfl_xor_sync(0xffffffffu, mx0, 2));
    mx1 = fmaxf(mx1, __shfl_xor_sync(0xffffffffu, mx1, 1));
    mx1 = fmaxf(mx1, __shfl_xor_sync(0xffffffffu, mx1, 2));
    float s0 = 0.f, s1 = 0.f;
#pragma unroll
    for (int j = 0; j < 16; ++j) {
        sacc[j][0] = __expf(sacc[j][0] - mx0);
        sacc[j][1] = __expf(sacc[j][1] - mx0);
        sacc[j][2] = __expf(sacc[j][2] - mx1);
        sacc[j][3] = __expf(sacc[j][3] - mx1);
        s0 += sacc[j][0] + sacc[j][1];
        s1 += sacc[j][2] + sacc[j][3];
    }
    s0 += __shfl_xor_sync(0xffffffffu, s0, 1);
    s0 += __shfl_xor_sync(0xffffffffu, s0, 2);
    s1 += __shfl_xor_sync(0xffffffffu, s1, 1);
    s1 += __shfl_xor_sync(0xffffffffu, s1, 2);
    float inv0 = 1.0f / s0, inv1 = 1.0f / s1;

    float oacc[4][4];
#pragma unroll
    for (int dn = 0; dn < 4; ++dn)
#pragma unroll
        for (int c = 0; c < 4; ++c) oacc[dn][c] = 0.f;
#pragma unroll
    for (int kk = 0; kk < 8; ++kk) {
        uint32_t aH[4];
        aH[0] = pk2h(sacc[2 * kk][0],     sacc[2 * kk][1]);
        aH[1] = pk2h(sacc[2 * kk][2],     sacc[2 * kk][3]);
        aH[2] = pk2h(sacc[2 * kk + 1][0], sacc[2 * kk + 1][1]);
        aH[3] = pk2h(sacc[2 * kk + 1][2], sacc[2 * kk + 1][3]);
#pragma unroll
        for (int dnp = 0; dnp < 2; ++dnp) {
            uint32_t ba = va + (uint32_t)(kk * 16 * 80 + dnp * 32);
            uint32_t bh[4], bl[4];
            LDM4T(bh, ba);
            LDM4T(bl, ba + (A_VL - A_VH));
            MMA4(oacc[2 * dnp], oacc[2 * dnp + 1], aH, bh, bl);
        }
    }

    // ctx: single fp16 store
    uint32_t* cp0 = g_ctxh + ((size_t)b * NTOK + row0) * 64 + h * 16 + (lane & 3);
#pragma unroll
    for (int dn = 0; dn < 4; ++dn) {
        cp0[dn * 4] = pk2h(oacc[dn][0] * inv0, oacc[dn][1] * inv0);
        cp0[8 * 64 + dn * 4] = pk2h(oacc[dn][2] * inv1, oacc[dn][3] * inv1);
    }
}

// ---------- launch ----------
extern "C" void kernel_launch(void* const* d_in, const int* in_sizes, int n_in,
                              void* d_out, int out_size) {
    const float* x          = (const float*)d_in[0];
    const int*   rpi        = (const int*)d_in[1];
    const float* mask       = (const float*)d_in[2];
    const float* sp_mask    = (const float*)d_in[3];
    const float* w_qkv      = (const float*)d_in[4];
    const float* b_qkv      = (const float*)d_in[5];
    const float* bias_table = (const float*)d_in[6];
    const float* w_proj     = (const float*)d_in[7];
    const float* b_proj     = (const float*)d_in[8];
    float* out = (float*)d_out;

    cudaFuncSetAttribute((const void*)qkv_mma_kernel,
                         cudaFuncAttributeMaxDynamicSharedMemorySize, GEMM_SMEM);
    cudaFuncSetAttribute((const void*)proj_mma_kernel,
                         cudaFuncAttributeMaxDynamicSharedMemorySize, GEMM_SMEM);
    cudaFuncSetAttribute((const void*)att_mma_kernel,
                         cudaFuncAttributeMaxDynamicSharedMemorySize, ATT_SMEM);

    prep_cmrp_kernel<<<4096, 256>>>(mask, sp_mask, rpi, bias_table);
    conv_w_kernel<<<24, 256>>>(w_qkv, 6144, 0);
    conv_w_kernel<<<8, 256>>>(w_proj, 2048, 1);
    qkv_mma_kernel<<<BWIN, 256, GEMM_SMEM>>>(x, b_qkv);
    att_mma_kernel<<<dim3(BWIN, HEADS), 256, ATT_SMEM>>>();
    proj_mma_kernel<<<BWIN, 256, GEMM_SMEM>>>(b_proj, out);
}